// round 1
// baseline (speedup 1.0000x reference)
#include <cuda_runtime.h>
#include <cstdint>

#define BB 4
#define NN 1024
#define DD 512
#define HH 8
#define EE 5
#define HDIM 64

// ---------------- scratch (device globals; no allocation allowed) ----------------
__device__ float g_q[BB * HH * NN * HDIM];
__device__ float g_k[BB * HH * NN * HDIM];
__device__ float g_v[BB * HH * NN * HDIM];
__device__ float g_att[BB * NN * DD];
__device__ int   g_mask[BB * NN];
__device__ int   g_any[BB];

// ---------------- FMA-only exp (avoids MUFU wall: 67M exps) ----------------
// exp(x) for x <= 0 (inputs are always <= 0 here). Clamped so -1e30 sentinels -> ~0.
__device__ __forceinline__ float fast_exp(float x) {
    x = fmaxf(x, -87.0f);
    const float L2E = 1.4426950408889634f;
    float z = fmaf(x, L2E, 12582912.0f);          // round(x*log2e) via magic number
    float nf = z - 12582912.0f;
    int   n  = __float_as_int(z) - 0x4B400000;    // integer part
    float r  = fmaf(x, L2E, -nf);                 // r in [-0.5, 0.5]
    // 2^r, degree-5 Taylor in ln2 (rel err ~7e-7 on the interval)
    float p = 0.0013333558146428443f;
    p = fmaf(p, r, 0.009618129107628477f);
    p = fmaf(p, r, 0.05550410866482158f);
    p = fmaf(p, r, 0.2402265069591007f);
    p = fmaf(p, r, 0.6931471805599453f);
    p = fmaf(p, r, 1.0f);
    return __int_as_float(__float_as_int(p) + (n << 23));
}

// ---------------- kernel 0: mask layout detection + canonicalization ----------------
// node_mask may arrive as bool (1B), int32, or float32. Detect from bit patterns.
__global__ void mask_prep_kernel(const unsigned* __restrict__ mraw) {
    __shared__ int s_int, s_float;
    __shared__ int s_any[BB];
    int t = threadIdx.x;  // 1024 threads
    if (t == 0) { s_int = 1; s_float = 1; }
    if (t < BB) s_any[t] = 0;
    __syncthreads();
    // First 1024 words are in-bounds for every candidate layout (bool => exactly 4096B).
    unsigned v = mraw[t];
    if (v > 1u) atomicAnd(&s_int, 0);
    if (!(v == 0u || v == 0x3F800000u)) atomicAnd(&s_float, 0);
    __syncthreads();
    int mode = s_int ? 0 : (s_float ? 1 : 2);  // 0=int32, 1=float32, 2=bytes
    for (int i = t; i < BB * NN; i += 1024) {
        int val;
        if (mode == 0)      val = ((const int*)mraw)[i];
        else if (mode == 1) val = (((const unsigned*)mraw)[i] != 0u);
        else                val = ((const unsigned char*)mraw)[i];
        val = val ? 1 : 0;
        g_mask[i] = val;
        if (val) atomicOr(&s_any[i >> 10], 1);
    }
    __syncthreads();
    if (t < BB) g_any[t] = s_any[t];
}

// ---------------- kernel 1: qkv = x @ w_qkv^T, scattered into (B,H,N,64) ----------------
// M=4096, N=1536, K=512. 64x64 tile, 4x4 per thread, 256 threads.
__global__ __launch_bounds__(256) void qkv_gemm_kernel(const float* __restrict__ X,
                                                       const float* __restrict__ W) {
    __shared__ float sA[16][64];
    __shared__ float sB[16][64];
    int tid = threadIdx.x;
    int tx = tid & 15, ty = tid >> 4;
    int rowBase = blockIdx.y * 64;
    int colBase = blockIdx.x * 64;
    int lr = tid >> 2;        // 0..63
    int lk = (tid & 3) * 4;   // 0,4,8,12

    float acc[4][4];
#pragma unroll
    for (int i = 0; i < 4; i++)
#pragma unroll
        for (int j = 0; j < 4; j++) acc[i][j] = 0.f;

    const float* Aptr = X + (rowBase + lr) * DD + lk;
    const float* Bptr = W + (colBase + lr) * DD + lk;

    for (int k0 = 0; k0 < DD; k0 += 16) {
        float4 a = *(const float4*)(Aptr + k0);
        float4 bq = *(const float4*)(Bptr + k0);
        sA[lk + 0][lr] = a.x; sA[lk + 1][lr] = a.y; sA[lk + 2][lr] = a.z; sA[lk + 3][lr] = a.w;
        sB[lk + 0][lr] = bq.x; sB[lk + 1][lr] = bq.y; sB[lk + 2][lr] = bq.z; sB[lk + 3][lr] = bq.w;
        __syncthreads();
#pragma unroll
        for (int kk = 0; kk < 16; kk++) {
            float4 av = *(const float4*)&sA[kk][ty * 4];
            float4 bv = *(const float4*)&sB[kk][tx * 4];
            float ar[4] = {av.x, av.y, av.z, av.w};
            float br[4] = {bv.x, bv.y, bv.z, bv.w};
#pragma unroll
            for (int i = 0; i < 4; i++)
#pragma unroll
                for (int j = 0; j < 4; j++) acc[i][j] = fmaf(ar[i], br[j], acc[i][j]);
        }
        __syncthreads();
    }
    // scatter into q/k/v with (B,H,N,HD) layout
    int col0 = colBase + tx * 4;
    int sect = col0 >> 9;          // 0=q,1=k,2=v (tile never straddles: 64 | 512)
    int d0 = col0 & 511;
    int h = d0 >> 6;
    int hd0 = d0 & 63;             // multiple of 4
    float* dst = (sect == 0) ? g_q : ((sect == 1) ? g_k : g_v);
#pragma unroll
    for (int i = 0; i < 4; i++) {
        int row = rowBase + ty * 4 + i;
        int b = row >> 10, n = row & 1023;
        float4 o = make_float4(acc[i][0], acc[i][1], acc[i][2], acc[i][3]);
        *(float4*)&dst[((b * HH + h) * NN + n) * HDIM + hd0] = o;
    }
}

// ---------------- kernel 2: fused edge-aware attention ----------------
// block = (qtile of 64 queries, head, batch); 8 warps, warp handles 8 queries.
// K/V tiles (32 keys) staged in smem (pad 65 -> conflict-free). Edge read from L2
// (used exactly once per block; cross-head reuse happens in L2). Online softmax.
__global__ __launch_bounds__(256) void attn_kernel(const float* __restrict__ edge,
                                                   const float* __restrict__ w_ep,
                                                   const float* __restrict__ w_eg,
                                                   const float* __restrict__ b_eg) {
    __shared__ float sQ[64][65];
    __shared__ float sK[32][65];
    __shared__ float sV[32][65];
    __shared__ int   sKM[32];

    const int b = blockIdx.z, h = blockIdx.y, qt = blockIdx.x;
    const int n0 = qt * 64;
    const int tid = threadIdx.x;
    const int lane = tid & 31;
    const int w = tid >> 5;
    const int wq0 = w * 8;

    float wep[EE], weg[EE];
#pragma unroll
    for (int e = 0; e < EE; e++) {
        wep[e] = __ldg(&w_ep[h * EE + e]);
        weg[e] = __ldg(&w_eg[h * EE + e]);
    }
    const float beg = __ldg(&b_eg[h]);
    const int anyv = g_any[b];

    // load Q tile (64 x 64)
    const float* qbase = g_q + ((b * HH + h) * NN + n0) * HDIM;
    for (int i = tid; i < 1024; i += 256) {   // 1024 float4
        int row = i >> 4, c4 = (i & 15) * 4;
        float4 qv = *(const float4*)(qbase + row * HDIM + c4);
        sQ[row][c4] = qv.x; sQ[row][c4 + 1] = qv.y; sQ[row][c4 + 2] = qv.z; sQ[row][c4 + 3] = qv.w;
    }

    unsigned qmb = 0;
#pragma unroll
    for (int qq = 0; qq < 8; qq++)
        if (g_mask[b * NN + n0 + wq0 + qq]) qmb |= (1u << qq);

    float oA[8], oB[8], mr[8], sr[8];
#pragma unroll
    for (int qq = 0; qq < 8; qq++) { oA[qq] = 0.f; oB[qq] = 0.f; mr[qq] = -1e30f; sr[qq] = 0.f; }

    const float* kbase = g_k + (size_t)(b * HH + h) * NN * HDIM;
    const float* vbase = g_v + (size_t)(b * HH + h) * NN * HDIM;

    for (int m0 = 0; m0 < NN; m0 += 32) {
        __syncthreads();
        for (int i = tid; i < 512; i += 256) {   // 512 float4 for K (and V)
            int row = i >> 4, c4 = (i & 15) * 4;
            float4 kv = *(const float4*)(kbase + (m0 + row) * HDIM + c4);
            sK[row][c4] = kv.x; sK[row][c4 + 1] = kv.y; sK[row][c4 + 2] = kv.z; sK[row][c4 + 3] = kv.w;
            float4 vv = *(const float4*)(vbase + (m0 + row) * HDIM + c4);
            sV[row][c4] = vv.x; sV[row][c4 + 1] = vv.y; sV[row][c4 + 2] = vv.z; sV[row][c4 + 3] = vv.w;
        }
        if (tid < 32) sKM[tid] = g_mask[b * NN + m0 + tid];
        __syncthreads();

        // --- scores: lane = key, 8 queries per warp ---
        float sc[8];
#pragma unroll
        for (int qq = 0; qq < 8; qq++) sc[qq] = 0.f;
#pragma unroll 8
        for (int d = 0; d < 64; d++) {
            float kd = sK[lane][d];
#pragma unroll
            for (int qq = 0; qq < 8; qq++) sc[qq] = fmaf(sQ[wq0 + qq][d], kd, sc[qq]);
        }

        const int kvalid = sKM[lane];
        const int mg = m0 + lane;
#pragma unroll
        for (int qq = 0; qq < 8; qq++) {
            const float* ep = edge + (((b * NN + n0 + wq0 + qq) * NN) + mg) * EE;
            float e0 = __ldg(ep), e1 = __ldg(ep + 1), e2 = __ldg(ep + 2),
                  e3 = __ldg(ep + 3), e4 = __ldg(ep + 4);
            float biasv = e0 * wep[0];
            biasv = fmaf(e1, wep[1], biasv);
            biasv = fmaf(e2, wep[2], biasv);
            biasv = fmaf(e3, wep[3], biasv);
            biasv = fmaf(e4, wep[4], biasv);
            float gv = fmaf(e0, weg[0], beg);
            gv = fmaf(e1, weg[1], gv);
            gv = fmaf(e2, weg[2], gv);
            gv = fmaf(e3, weg[3], gv);
            gv = fmaf(e4, weg[4], gv);
            float gate = __fdividef(1.f, 1.f + fast_exp(-gv));  // 1 MUFU RCP only
            float s = fmaf(gate, biasv, sc[qq] * 0.125f);
            bool qv = (qmb >> qq) & 1;
            bool rowv = qv && anyv;
            bool pairv = qv && kvalid;
            // invalid row -> score 0 everywhere => uniform softmax (matches reference)
            sc[qq] = rowv ? (pairv ? s : -1e30f) : 0.0f;
        }

        // --- online softmax update ---
#pragma unroll
        for (int qq = 0; qq < 8; qq++) {
            float mt = sc[qq];
#pragma unroll
            for (int o = 16; o > 0; o >>= 1) mt = fmaxf(mt, __shfl_xor_sync(0xffffffffu, mt, o));
            float mn = fmaxf(mr[qq], mt);
            float al = fast_exp(mr[qq] - mn);
            float p = fast_exp(sc[qq] - mn);
            float ps = p;
#pragma unroll
            for (int o = 16; o > 0; o >>= 1) ps += __shfl_xor_sync(0xffffffffu, ps, o);
            sr[qq] = fmaf(sr[qq], al, ps);
            mr[qq] = mn;
            oA[qq] *= al;
            oB[qq] *= al;
            sc[qq] = p;  // probability for this lane's key
        }

        // --- P @ V: broadcast probs via shuffle, V rows from smem ---
#pragma unroll 4
        for (int j = 0; j < 32; j++) {
            float vA = sV[j][lane];
            float vB = sV[j][lane + 32];
#pragma unroll
            for (int qq = 0; qq < 8; qq++) {
                float pj = __shfl_sync(0xffffffffu, sc[qq], j);
                oA[qq] = fmaf(pj, vA, oA[qq]);
                oB[qq] = fmaf(pj, vB, oB[qq]);
            }
        }
    }

    // epilogue: normalize, write (B,N,D) with d = h*64 + hd
#pragma unroll
    for (int qq = 0; qq < 8; qq++) {
        float inv = __fdividef(1.f, sr[qq]);   // sr >= 1 always (valid rows have a p==1)
        int n = n0 + wq0 + qq;
        float* op = g_att + (b * NN + n) * DD + h * HDIM;
        op[lane] = oA[qq] * inv;
        op[lane + 32] = oB[qq] * inv;
    }
}

// ---------------- kernel 3: out = attnout @ w_proj^T + b_proj ----------------
__global__ __launch_bounds__(256) void proj_gemm_kernel(const float* __restrict__ W,
                                                        const float* __restrict__ bias,
                                                        float* __restrict__ out) {
    __shared__ float sA[16][64];
    __shared__ float sB[16][64];
    int tid = threadIdx.x;
    int tx = tid & 15, ty = tid >> 4;
    int rowBase = blockIdx.y * 64;
    int colBase = blockIdx.x * 64;
    int lr = tid >> 2;
    int lk = (tid & 3) * 4;

    float acc[4][4];
#pragma unroll
    for (int i = 0; i < 4; i++)
#pragma unroll
        for (int j = 0; j < 4; j++) acc[i][j] = 0.f;

    const float* Aptr = g_att + (rowBase + lr) * DD + lk;
    const float* Bptr = W + (colBase + lr) * DD + lk;

    for (int k0 = 0; k0 < DD; k0 += 16) {
        float4 a = *(const float4*)(Aptr + k0);
        float4 bq = *(const float4*)(Bptr + k0);
        sA[lk + 0][lr] = a.x; sA[lk + 1][lr] = a.y; sA[lk + 2][lr] = a.z; sA[lk + 3][lr] = a.w;
        sB[lk + 0][lr] = bq.x; sB[lk + 1][lr] = bq.y; sB[lk + 2][lr] = bq.z; sB[lk + 3][lr] = bq.w;
        __syncthreads();
#pragma unroll
        for (int kk = 0; kk < 16; kk++) {
            float4 av = *(const float4*)&sA[kk][ty * 4];
            float4 bv = *(const float4*)&sB[kk][tx * 4];
            float ar[4] = {av.x, av.y, av.z, av.w};
            float br[4] = {bv.x, bv.y, bv.z, bv.w};
#pragma unroll
            for (int i = 0; i < 4; i++)
#pragma unroll
                for (int j = 0; j < 4; j++) acc[i][j] = fmaf(ar[i], br[j], acc[i][j]);
        }
        __syncthreads();
    }
    int col0 = colBase + tx * 4;
    float4 bv4 = *(const float4*)(bias + col0);
#pragma unroll
    for (int i = 0; i < 4; i++) {
        int row = rowBase + ty * 4 + i;
        float4 o = make_float4(acc[i][0] + bv4.x, acc[i][1] + bv4.y,
                               acc[i][2] + bv4.z, acc[i][3] + bv4.w);
        *(float4*)&out[row * DD + col0] = o;
    }
}

// ---------------- launch ----------------
extern "C" void kernel_launch(void* const* d_in, const int* in_sizes, int n_in,
                              void* d_out, int out_size) {
    const float* x      = (const float*)d_in[0];
    const float* edge   = (const float*)d_in[1];
    const void*  mask   = d_in[2];
    const float* w_qkv  = (const float*)d_in[3];
    const float* w_ep   = (const float*)d_in[4];
    const float* w_eg   = (const float*)d_in[5];
    const float* b_eg   = (const float*)d_in[6];
    const float* w_proj = (const float*)d_in[7];
    const float* b_proj = (const float*)d_in[8];
    float* out = (float*)d_out;

    mask_prep_kernel<<<1, 1024>>>((const unsigned*)mask);

    dim3 g1(1536 / 64, 4096 / 64);
    qkv_gemm_kernel<<<g1, 256>>>(x, w_qkv);

    dim3 ga(NN / 64, HH, BB);
    attn_kernel<<<ga, 256>>>(edge, w_ep, w_eg, b_eg);

    dim3 g2(DD / 64, 4096 / 64);
    proj_gemm_kernel<<<g2, 256>>>(w_proj, b_proj, out);
}

// round 3
// speedup vs baseline: 1.2867x; 1.2867x over previous
#include <cuda_runtime.h>
#include <cuda_bf16.h>
#include <cstdint>

#define BB 4
#define NN 1024
#define DD 512
#define HH 8
#define EE 5
#define HDIM 64

// ---------------- scratch (device globals; no allocation allowed) ----------------
__device__ float g_q[BB * HH * NN * HDIM];
__device__ float g_k[BB * HH * NN * HDIM];
__device__ float g_v[BB * HH * NN * HDIM];
__device__ int   g_mask[BB * NN];
__device__ int   g_any[BB];
// bf16 hi/lo operand splits
__device__ __nv_bfloat16 g_xhi[BB * NN * DD],   g_xlo[BB * NN * DD];
__device__ __nv_bfloat16 g_wqkvhi[3 * DD * DD], g_wqkvlo[3 * DD * DD];
__device__ __nv_bfloat16 g_atthi[BB * NN * DD], g_attlo[BB * NN * DD];
__device__ __nv_bfloat16 g_wprojhi[DD * DD],    g_wprojlo[DD * DD];

// ---------------- helpers ----------------
__device__ __forceinline__ uint32_t smem_u32(const void* p) {
    return (uint32_t)__cvta_generic_to_shared(p);
}
__device__ __forceinline__ void ldsm4(uint32_t& r0, uint32_t& r1, uint32_t& r2, uint32_t& r3,
                                      uint32_t a) {
    asm volatile("ldmatrix.sync.aligned.m8n8.x4.shared.b16 {%0,%1,%2,%3}, [%4];"
                 : "=r"(r0), "=r"(r1), "=r"(r2), "=r"(r3) : "r"(a));
}
__device__ __forceinline__ void mma16816(float* c, uint32_t a0, uint32_t a1, uint32_t a2,
                                         uint32_t a3, uint32_t b0, uint32_t b1) {
    asm volatile(
        "mma.sync.aligned.m16n8k16.row.col.f32.bf16.bf16.f32 "
        "{%0,%1,%2,%3}, {%4,%5,%6,%7}, {%8,%9}, {%0,%1,%2,%3};"
        : "+f"(c[0]), "+f"(c[1]), "+f"(c[2]), "+f"(c[3])
        : "r"(a0), "r"(a1), "r"(a2), "r"(a3), "r"(b0), "r"(b1));
}
__device__ __forceinline__ void cp_async16(uint32_t saddr, const void* gaddr) {
    asm volatile("cp.async.ca.shared.global [%0], [%1], 16;" :: "r"(saddr), "l"(gaddr));
}
__device__ __forceinline__ void cp_commit() {
    asm volatile("cp.async.commit_group;" ::: "memory");
}
template <int N>
__device__ __forceinline__ void cp_wait() {
    asm volatile("cp.async.wait_group %0;" :: "n"(N) : "memory");
}

// ---------------- FMA-only exp (avoids MUFU wall) ----------------
__device__ __forceinline__ float fast_exp(float x) {
    x = fmaxf(x, -87.0f);
    const float L2E = 1.4426950408889634f;
    float z = fmaf(x, L2E, 12582912.0f);
    float nf = z - 12582912.0f;
    int   n  = __float_as_int(z) - 0x4B400000;
    float r  = fmaf(x, L2E, -nf);
    float p = 0.0013333558146428443f;
    p = fmaf(p, r, 0.009618129107628477f);
    p = fmaf(p, r, 0.05550410866482158f);
    p = fmaf(p, r, 0.2402265069591007f);
    p = fmaf(p, r, 0.6931471805599453f);
    p = fmaf(p, r, 1.0f);
    return __int_as_float(__float_as_int(p) + (n << 23));
}

// ---------------- kernel 0: mask canonicalization ----------------
__global__ void mask_prep_kernel(const unsigned* __restrict__ mraw) {
    __shared__ int s_int, s_float;
    __shared__ int s_any[BB];
    int t = threadIdx.x;
    if (t == 0) { s_int = 1; s_float = 1; }
    if (t < BB) s_any[t] = 0;
    __syncthreads();
    unsigned v = mraw[t];
    if (v > 1u) atomicAnd(&s_int, 0);
    if (!(v == 0u || v == 0x3F800000u)) atomicAnd(&s_float, 0);
    __syncthreads();
    int mode = s_int ? 0 : (s_float ? 1 : 2);
    for (int i = t; i < BB * NN; i += 1024) {
        int val;
        if (mode == 0)      val = ((const int*)mraw)[i];
        else if (mode == 1) val = (((const unsigned*)mraw)[i] != 0u);
        else                val = ((const unsigned char*)mraw)[i];
        val = val ? 1 : 0;
        g_mask[i] = val;
        if (val) atomicOr(&s_any[i >> 10], 1);
    }
    __syncthreads();
    if (t < BB) g_any[t] = s_any[t];
}

// ---------------- kernel 0b: fp32 -> bf16 hi/lo split ----------------
__global__ void cvt_kernel(const float* __restrict__ src, int n, int which) {
    __nv_bfloat16* hi = (which == 0) ? g_xhi : (which == 1) ? g_wqkvhi : g_wprojhi;
    __nv_bfloat16* lo = (which == 0) ? g_xlo : (which == 1) ? g_wqkvlo : g_wprojlo;
    int i = blockIdx.x * 256 + threadIdx.x;
    if (i < n) {
        float v = src[i];
        __nv_bfloat16 h = __float2bfloat16(v);
        hi[i] = h;
        lo[i] = __float2bfloat16(v - __bfloat162float(h));
    }
}

// ---------------- mma.sync bf16x3 GEMM: D[4096, ncols] = A @ B^T ----------------
// Block tile 128x128, 8 warps (4 M x 2 N), warp tile 32x64.
// K_eff = 3*512 staged in 24 chunks of 64 bf16, cp.async double-buffered.
// mode 0: A=x(hi/lo), B=w_qkv(hi/lo) -> scatter g_q/g_k/g_v. mode 1: proj + bias.
__global__ __launch_bounds__(256) void mma_gemm_kernel(const float* __restrict__ bias,
                                                       float* __restrict__ outp, int mode) {
    extern __shared__ __align__(128) char sm[];   // 2 stages x (A 16KB | B 16KB)
    const int tid = threadIdx.x;
    const int wid = tid >> 5, lane = tid & 31;
    const int wm = wid >> 1, wn = wid & 1;        // warp grid 4x2
    const int mb = blockIdx.y, cb = blockIdx.x;

    const __nv_bfloat16* Ahi = (mode == 0) ? g_xhi : g_atthi;
    const __nv_bfloat16* Alo = (mode == 0) ? g_xlo : g_attlo;
    const __nv_bfloat16* Bhi = (mode == 0) ? g_wqkvhi : g_wprojhi;
    const __nv_bfloat16* Blo = (mode == 0) ? g_wqkvlo : g_wprojlo;

    // loader: 2048 16B units per chunk (A:0-1023, B:1024-2047), 8 per thread
    // unit u (within matrix): r = u>>3, ch = u&7; smem: r*128 + ((ch ^ (r&7))<<4)
    const uint32_t sbase = smem_u32(sm);

    // ldmatrix addresses (per lane, per stage-invariant row bases)
    // A tiles: mt in {0,1}: row = wm*32 + mt*16 + (lane&15), chunk k-half = lane>>4
    int arow[2], axc[2];
#pragma unroll
    for (int mt = 0; mt < 2; mt++) {
        int r = wm * 32 + mt * 16 + (lane & 15);
        arow[mt] = r * 128;
        axc[mt] = r & 7;
    }
    const int akh = lane >> 4;
    // B tiles: j in 0..3 covers n8-tiles {2j, 2j+1}:
    // row = wn*64 + j*16 + ((lane>>4)<<3) + (lane&7), k-half = (lane>>3)&1
    int brow[4], bxc[4];
#pragma unroll
    for (int j = 0; j < 4; j++) {
        int r = wn * 64 + j * 16 + ((lane >> 4) << 3) + (lane & 7);
        brow[j] = r * 128;
        bxc[j] = r & 7;
    }
    const int bkh = (lane >> 3) & 1;

    float acc[2][8][4];
#pragma unroll
    for (int mt = 0; mt < 2; mt++)
#pragma unroll
        for (int n8 = 0; n8 < 8; n8++)
#pragma unroll
            for (int q = 0; q < 4; q++) acc[mt][n8][q] = 0.f;

    const int NC = 24;   // 3 segs x 8 k-chunks
    auto load_chunk = [&](int c, int stage) {
        int seg = c >> 3, kc = c & 7;
        const __nv_bfloat16* As = (seg == 2) ? Alo : Ahi;
        const __nv_bfloat16* Bs = (seg == 1) ? Blo : Bhi;
        uint32_t st = sbase + stage * 32768;
#pragma unroll
        for (int u8 = 0; u8 < 8; u8++) {
            int u = tid * 8 + u8;           // 0..2047
            int isB = u >> 10;
            int uu = u & 1023;
            int r = uu >> 3, ch = uu & 7;
            const __nv_bfloat16* src = isB
                ? (Bs + (size_t)(cb * 128 + r) * DD + kc * 64 + ch * 8)
                : (As + (size_t)(mb * 128 + r) * DD + kc * 64 + ch * 8);
            uint32_t sa = st + isB * 16384 + r * 128 + ((ch ^ (r & 7)) << 4);
            cp_async16(sa, src);
        }
        cp_commit();
    };

    load_chunk(0, 0);
    for (int c = 0; c < NC; c++) {
        if (c + 1 < NC) load_chunk(c + 1, (c + 1) & 1);
        if (c + 1 < NC) cp_wait<1>(); else cp_wait<0>();
        __syncthreads();
        uint32_t sA = sbase + (c & 1) * 32768;
        uint32_t sB = sA + 16384;
#pragma unroll
        for (int k16 = 0; k16 < 4; k16++) {
            uint32_t a[2][4];
#pragma unroll
            for (int mt = 0; mt < 2; mt++) {
                uint32_t ad = sA + arow[mt] + (((k16 * 2 + akh) ^ axc[mt]) << 4);
                ldsm4(a[mt][0], a[mt][1], a[mt][2], a[mt][3], ad);
            }
#pragma unroll
            for (int j = 0; j < 4; j++) {
                uint32_t b0, b1, b2, b3;
                uint32_t bd = sB + brow[j] + (((k16 * 2 + bkh) ^ bxc[j]) << 4);
                ldsm4(b0, b1, b2, b3, bd);
                mma16816(acc[0][2 * j],     a[0][0], a[0][1], a[0][2], a[0][3], b0, b1);
                mma16816(acc[0][2 * j + 1], a[0][0], a[0][1], a[0][2], a[0][3], b2, b3);
                mma16816(acc[1][2 * j],     a[1][0], a[1][1], a[1][2], a[1][3], b0, b1);
                mma16816(acc[1][2 * j + 1], a[1][0], a[1][1], a[1][2], a[1][3], b2, b3);
            }
        }
        __syncthreads();
    }

    // epilogue: c0,c1 -> (row, col..col+1); c2,c3 -> (row+8, ...)
    const int colw = cb * 128 + wn * 64;
    const int roww = mb * 128 + wm * 32;
#pragma unroll
    for (int mt = 0; mt < 2; mt++) {
#pragma unroll
        for (int n8 = 0; n8 < 8; n8++) {
            int col = colw + n8 * 8 + (lane & 3) * 2;
            int row = roww + mt * 16 + (lane >> 2);
            if (mode == 0) {
                int sect = col >> 9, d = col & 511;
                int h = d >> 6, hd = d & 63;
                float* dst = (sect == 0) ? g_q : ((sect == 1) ? g_k : g_v);
                int b = row >> 10, n = row & 1023;
                size_t base = ((size_t)((b * HH + h) * NN) + n) * HDIM + hd;
                *(float2*)&dst[base] = make_float2(acc[mt][n8][0], acc[mt][n8][1]);
                *(float2*)&dst[base + 8 * HDIM] = make_float2(acc[mt][n8][2], acc[mt][n8][3]);
            } else {
                float b0 = bias[col], b1 = bias[col + 1];
                *(float2*)&outp[(size_t)row * DD + col] =
                    make_float2(acc[mt][n8][0] + b0, acc[mt][n8][1] + b1);
                *(float2*)&outp[(size_t)(row + 8) * DD + col] =
                    make_float2(acc[mt][n8][2] + b0, acc[mt][n8][3] + b1);
            }
        }
    }
}

// ---------------- kernel 2: fused edge-aware attention (SIMT) ----------------
__global__ __launch_bounds__(256) void attn_kernel(const float* __restrict__ edge,
                                                   const float* __restrict__ w_ep,
                                                   const float* __restrict__ w_eg,
                                                   const float* __restrict__ b_eg) {
    __shared__ __align__(16) float sQ[64 * 68];
    __shared__ __align__(16) float sK[32 * 68];
    __shared__ __align__(16) float sV[32 * 68];
    __shared__ __align__(16) float sP[64 * 36];
    __shared__ int sKM[32];

    const int b = blockIdx.z, h = blockIdx.y, qt = blockIdx.x;
    const int n0 = qt * 64;
    const int tid = threadIdx.x;
    const int lane = tid & 31;
    const int w = tid >> 5;
    const int wq0 = w * 8;

    float wep[EE], weg[EE];
#pragma unroll
    for (int e = 0; e < EE; e++) {
        wep[e] = __ldg(&w_ep[h * EE + e]);
        weg[e] = __ldg(&w_eg[h * EE + e]);
    }
    const float beg = __ldg(&b_eg[h]);
    const int anyv = g_any[b];

    const float* qbase = g_q + ((size_t)(b * HH + h) * NN + n0) * HDIM;
    for (int i = tid; i < 1024; i += 256) {
        int r = i >> 4, c4 = (i & 15) * 4;
        *(float4*)(sQ + r * 68 + c4) = *(const float4*)(qbase + r * HDIM + c4);
    }

    unsigned qmb = 0;
#pragma unroll
    for (int qq = 0; qq < 8; qq++)
        if (g_mask[b * NN + n0 + wq0 + qq]) qmb |= (1u << qq);

    float oA[8], oB[8], mr[8], sr[8];
#pragma unroll
    for (int qq = 0; qq < 8; qq++) { oA[qq] = 0.f; oB[qq] = 0.f; mr[qq] = -1e30f; sr[qq] = 0.f; }

    const float* kbase = g_k + (size_t)(b * HH + h) * NN * HDIM;
    const float* vbase = g_v + (size_t)(b * HH + h) * NN * HDIM;

    for (int m0 = 0; m0 < NN; m0 += 32) {
        __syncthreads();
        for (int i = tid; i < 512; i += 256) {
            int r = i >> 4, c4 = (i & 15) * 4;
            *(float4*)(sK + r * 68 + c4) = *(const float4*)(kbase + (m0 + r) * HDIM + c4);
            *(float4*)(sV + r * 68 + c4) = *(const float4*)(vbase + (m0 + r) * HDIM + c4);
        }
        if (tid < 32) sKM[tid] = g_mask[b * NN + m0 + tid];
        __syncthreads();

        float sc[8];
#pragma unroll
        for (int qq = 0; qq < 8; qq++) sc[qq] = 0.f;
        const float4* k4 = (const float4*)(sK + lane * 68);
#pragma unroll
        for (int d4 = 0; d4 < 16; d4++) {
            float4 kv = k4[d4];
#pragma unroll
            for (int qq = 0; qq < 8; qq++) {
                float4 qv = *(const float4*)(sQ + (wq0 + qq) * 68 + d4 * 4);
                sc[qq] = fmaf(qv.x, kv.x, sc[qq]);
                sc[qq] = fmaf(qv.y, kv.y, sc[qq]);
                sc[qq] = fmaf(qv.z, kv.z, sc[qq]);
                sc[qq] = fmaf(qv.w, kv.w, sc[qq]);
            }
        }

        const int kvalid = sKM[lane];
        const int mg = m0 + lane;
#pragma unroll
        for (int qq = 0; qq < 8; qq++) {
            const float* ep = edge + (((b * NN + n0 + wq0 + qq) * NN) + mg) * EE;
            float e0 = __ldg(ep), e1 = __ldg(ep + 1), e2 = __ldg(ep + 2),
                  e3 = __ldg(ep + 3), e4 = __ldg(ep + 4);
            float biasv = e0 * wep[0];
            biasv = fmaf(e1, wep[1], biasv);
            biasv = fmaf(e2, wep[2], biasv);
            biasv = fmaf(e3, wep[3], biasv);
            biasv = fmaf(e4, wep[4], biasv);
            float gv = fmaf(e0, weg[0], beg);
            gv = fmaf(e1, weg[1], gv);
            gv = fmaf(e2, weg[2], gv);
            gv = fmaf(e3, weg[3], gv);
            gv = fmaf(e4, weg[4], gv);
            float gate = __fdividef(1.f, 1.f + fast_exp(-gv));
            float s = fmaf(gate, biasv, sc[qq] * 0.125f);
            bool qv = (qmb >> qq) & 1;
            bool rowv = qv && anyv;
            bool pairv = qv && kvalid;
            sc[qq] = rowv ? (pairv ? s : -1e30f) : 0.0f;
        }

#pragma unroll
        for (int qq = 0; qq < 8; qq++) {
            float mt = sc[qq];
#pragma unroll
            for (int o = 16; o > 0; o >>= 1) mt = fmaxf(mt, __shfl_xor_sync(0xffffffffu, mt, o));
            float mn = fmaxf(mr[qq], mt);
            float al = fast_exp(mr[qq] - mn);
            float p = fast_exp(sc[qq] - mn);
            float ps = p;
#pragma unroll
            for (int o = 16; o > 0; o >>= 1) ps += __shfl_xor_sync(0xffffffffu, ps, o);
            sr[qq] = fmaf(sr[qq], al, ps);
            mr[qq] = mn;
            oA[qq] *= al;
            oB[qq] *= al;
            sc[qq] = p;
        }

#pragma unroll
        for (int qq = 0; qq < 8; qq++) sP[(wq0 + qq) * 36 + lane] = sc[qq];
        __syncwarp();
#pragma unroll
        for (int j4 = 0; j4 < 8; j4++) {
            int j = j4 * 4;
            float vA0 = sV[(j + 0) * 68 + lane],      vA1 = sV[(j + 1) * 68 + lane];
            float vA2 = sV[(j + 2) * 68 + lane],      vA3 = sV[(j + 3) * 68 + lane];
            float vB0 = sV[(j + 0) * 68 + lane + 32], vB1 = sV[(j + 1) * 68 + lane + 32];
            float vB2 = sV[(j + 2) * 68 + lane + 32], vB3 = sV[(j + 3) * 68 + lane + 32];
#pragma unroll
            for (int qq = 0; qq < 8; qq++) {
                float4 p4 = *(const float4*)(sP + (wq0 + qq) * 36 + j);
                oA[qq] = fmaf(p4.x, vA0, oA[qq]);
                oA[qq] = fmaf(p4.y, vA1, oA[qq]);
                oA[qq] = fmaf(p4.z, vA2, oA[qq]);
                oA[qq] = fmaf(p4.w, vA3, oA[qq]);
                oB[qq] = fmaf(p4.x, vB0, oB[qq]);
                oB[qq] = fmaf(p4.y, vB1, oB[qq]);
                oB[qq] = fmaf(p4.z, vB2, oB[qq]);
                oB[qq] = fmaf(p4.w, vB3, oB[qq]);
            }
        }
    }

    // epilogue: normalize, emit bf16 hi/lo for proj GEMM
#pragma unroll
    for (int qq = 0; qq < 8; qq++) {
        float inv = __fdividef(1.f, sr[qq]);
        int n = n0 + wq0 + qq;
        size_t base = (size_t)(b * NN + n) * DD + h * HDIM;
        float vA = oA[qq] * inv, vB = oB[qq] * inv;
        __nv_bfloat16 hA = __float2bfloat16(vA);
        __nv_bfloat16 hB = __float2bfloat16(vB);
        g_atthi[base + lane] = hA;
        g_attlo[base + lane] = __float2bfloat16(vA - __bfloat162float(hA));
        g_atthi[base + lane + 32] = hB;
        g_attlo[base + lane + 32] = __float2bfloat16(vB - __bfloat162float(hB));
    }
}

// ---------------- launch ----------------
extern "C" void kernel_launch(void* const* d_in, const int* in_sizes, int n_in,
                              void* d_out, int out_size) {
    const float* x      = (const float*)d_in[0];
    const float* edge   = (const float*)d_in[1];
    const void*  mask   = d_in[2];
    const float* w_qkv  = (const float*)d_in[3];
    const float* w_ep   = (const float*)d_in[4];
    const float* w_eg   = (const float*)d_in[5];
    const float* b_eg   = (const float*)d_in[6];
    const float* w_proj = (const float*)d_in[7];
    const float* b_proj = (const float*)d_in[8];
    float* out = (float*)d_out;

    static bool attr_done = false;
    if (!attr_done) {
        cudaFuncSetAttribute(mma_gemm_kernel, cudaFuncAttributeMaxDynamicSharedMemorySize, 65536);
        attr_done = true;
    }

    mask_prep_kernel<<<1, 1024>>>((const unsigned*)mask);

    cvt_kernel<<<(BB * NN * DD + 255) / 256, 256>>>(x, BB * NN * DD, 0);
    cvt_kernel<<<(3 * DD * DD + 255) / 256, 256>>>(w_qkv, 3 * DD * DD, 1);
    cvt_kernel<<<(DD * DD + 255) / 256, 256>>>(w_proj, DD * DD, 2);

    dim3 g1(12, 32);   // qkv: 1536 cols, 4096 rows
    mma_gemm_kernel<<<g1, 256, 65536>>>(nullptr, nullptr, 0);

    dim3 ga(NN / 64, HH, BB);
    attn_kernel<<<ga, 256>>>(edge, w_ep, w_eg, b_eg);

    dim3 g2(4, 32);    // proj: 512 cols, 4096 rows
    mma_gemm_kernel<<<g2, 256, 65536>>>(b_proj, out, 1);
}

// round 4
// speedup vs baseline: 1.5911x; 1.2366x over previous
#include <cuda_runtime.h>
#include <cuda_bf16.h>
#include <cstdint>

#define BB 4
#define NN 1024
#define DD 512
#define HH 8
#define EE 5
#define HDIM 64
#define QT 128
#define KT 64

// ---------------- scratch (device globals; no allocation allowed) ----------------
__device__ float g_q[BB * HH * NN * HDIM];
__device__ float g_k[BB * HH * NN * HDIM];
__device__ float g_v[BB * HH * NN * HDIM];
__device__ int   g_mask[BB * NN];
__device__ int   g_any[BB];
__device__ __nv_bfloat16 g_xhi[BB * NN * DD],   g_xlo[BB * NN * DD];
__device__ __nv_bfloat16 g_wqkvhi[3 * DD * DD], g_wqkvlo[3 * DD * DD];
__device__ __nv_bfloat16 g_atthi[BB * NN * DD], g_attlo[BB * NN * DD];
__device__ __nv_bfloat16 g_wprojhi[DD * DD],    g_wprojlo[DD * DD];

// ---------------- helpers ----------------
__device__ __forceinline__ uint32_t smem_u32(const void* p) {
    return (uint32_t)__cvta_generic_to_shared(p);
}
__device__ __forceinline__ void ldsm4(uint32_t& r0, uint32_t& r1, uint32_t& r2, uint32_t& r3,
                                      uint32_t a) {
    asm volatile("ldmatrix.sync.aligned.m8n8.x4.shared.b16 {%0,%1,%2,%3}, [%4];"
                 : "=r"(r0), "=r"(r1), "=r"(r2), "=r"(r3) : "r"(a));
}
__device__ __forceinline__ void mma16816(float* c, uint32_t a0, uint32_t a1, uint32_t a2,
                                         uint32_t a3, uint32_t b0, uint32_t b1) {
    asm volatile(
        "mma.sync.aligned.m16n8k16.row.col.f32.bf16.bf16.f32 "
        "{%0,%1,%2,%3}, {%4,%5,%6,%7}, {%8,%9}, {%0,%1,%2,%3};"
        : "+f"(c[0]), "+f"(c[1]), "+f"(c[2]), "+f"(c[3])
        : "r"(a0), "r"(a1), "r"(a2), "r"(a3), "r"(b0), "r"(b1));
}
__device__ __forceinline__ void cp_async16(uint32_t saddr, const void* gaddr) {
    asm volatile("cp.async.ca.shared.global [%0], [%1], 16;" :: "r"(saddr), "l"(gaddr));
}
__device__ __forceinline__ void cp_commit() {
    asm volatile("cp.async.commit_group;" ::: "memory");
}
template <int N>
__device__ __forceinline__ void cp_wait() {
    asm volatile("cp.async.wait_group %0;" :: "n"(N) : "memory");
}
// element index into row-major 64-bf16-wide smem tile, 16B xor-swizzled
__device__ __forceinline__ int swz(int r, int d) {
    return r * 64 + ((((d >> 3) ^ (r & 7)) << 3) | (d & 7));
}
__device__ __forceinline__ void pack_hilo(float p0, float p1, uint32_t& hi, uint32_t& lo) {
    __nv_bfloat16 h0 = __float2bfloat16(p0), h1 = __float2bfloat16(p1);
    hi = ((uint32_t)__bfloat16_as_ushort(h1) << 16) | (uint32_t)__bfloat16_as_ushort(h0);
    __nv_bfloat16 g0 = __float2bfloat16(p0 - __bfloat162float(h0));
    __nv_bfloat16 g1 = __float2bfloat16(p1 - __bfloat162float(h1));
    lo = ((uint32_t)__bfloat16_as_ushort(g1) << 16) | (uint32_t)__bfloat16_as_ushort(g0);
}

// ---------------- FMA-only exp ----------------
__device__ __forceinline__ float fast_exp(float x) {
    x = fmaxf(x, -87.0f);
    const float L2E = 1.4426950408889634f;
    float z = fmaf(x, L2E, 12582912.0f);
    float nf = z - 12582912.0f;
    int   n  = __float_as_int(z) - 0x4B400000;
    float r  = fmaf(x, L2E, -nf);
    float p = 0.0013333558146428443f;
    p = fmaf(p, r, 0.009618129107628477f);
    p = fmaf(p, r, 0.05550410866482158f);
    p = fmaf(p, r, 0.2402265069591007f);
    p = fmaf(p, r, 0.6931471805599453f);
    p = fmaf(p, r, 1.0f);
    return __int_as_float(__float_as_int(p) + (n << 23));
}

// ---------------- kernel 0: mask canonicalization ----------------
__global__ void mask_prep_kernel(const unsigned* __restrict__ mraw) {
    __shared__ int s_int, s_float;
    __shared__ int s_any[BB];
    int t = threadIdx.x;
    if (t == 0) { s_int = 1; s_float = 1; }
    if (t < BB) s_any[t] = 0;
    __syncthreads();
    unsigned v = mraw[t];
    if (v > 1u) atomicAnd(&s_int, 0);
    if (!(v == 0u || v == 0x3F800000u)) atomicAnd(&s_float, 0);
    __syncthreads();
    int mode = s_int ? 0 : (s_float ? 1 : 2);
    for (int i = t; i < BB * NN; i += 1024) {
        int val;
        if (mode == 0)      val = ((const int*)mraw)[i];
        else if (mode == 1) val = (((const unsigned*)mraw)[i] != 0u);
        else                val = ((const unsigned char*)mraw)[i];
        val = val ? 1 : 0;
        g_mask[i] = val;
        if (val) atomicOr(&s_any[i >> 10], 1);
    }
    __syncthreads();
    if (t < BB) g_any[t] = s_any[t];
}

// ---------------- kernel 0b: fp32 -> bf16 hi/lo split ----------------
__global__ void cvt_kernel(const float* __restrict__ src, int n, int which) {
    __nv_bfloat16* hi = (which == 0) ? g_xhi : (which == 1) ? g_wqkvhi : g_wprojhi;
    __nv_bfloat16* lo = (which == 0) ? g_xlo : (which == 1) ? g_wqkvlo : g_wprojlo;
    int i = blockIdx.x * 256 + threadIdx.x;
    if (i < n) {
        float v = src[i];
        __nv_bfloat16 h = __float2bfloat16(v);
        hi[i] = h;
        lo[i] = __float2bfloat16(v - __bfloat162float(h));
    }
}

// ---------------- mma.sync bf16x3 GEMM (verified in round 3) ----------------
__global__ __launch_bounds__(256) void mma_gemm_kernel(const float* __restrict__ bias,
                                                       float* __restrict__ outp, int mode) {
    extern __shared__ __align__(128) char sm[];
    const int tid = threadIdx.x;
    const int wid = tid >> 5, lane = tid & 31;
    const int wm = wid >> 1, wn = wid & 1;
    const int mb = blockIdx.y, cb = blockIdx.x;

    const __nv_bfloat16* Ahi = (mode == 0) ? g_xhi : g_atthi;
    const __nv_bfloat16* Alo = (mode == 0) ? g_xlo : g_attlo;
    const __nv_bfloat16* Bhi = (mode == 0) ? g_wqkvhi : g_wprojhi;
    const __nv_bfloat16* Blo = (mode == 0) ? g_wqkvlo : g_wprojlo;

    const uint32_t sbase = smem_u32(sm);

    int arow[2], axc[2];
#pragma unroll
    for (int mt = 0; mt < 2; mt++) {
        int r = wm * 32 + mt * 16 + (lane & 15);
        arow[mt] = r * 128;
        axc[mt] = r & 7;
    }
    const int akh = lane >> 4;
    int brow[4], bxc[4];
#pragma unroll
    for (int j = 0; j < 4; j++) {
        int r = wn * 64 + j * 16 + ((lane >> 4) << 3) + (lane & 7);
        brow[j] = r * 128;
        bxc[j] = r & 7;
    }
    const int bkh = (lane >> 3) & 1;

    float acc[2][8][4];
#pragma unroll
    for (int mt = 0; mt < 2; mt++)
#pragma unroll
        for (int n8 = 0; n8 < 8; n8++)
#pragma unroll
            for (int q = 0; q < 4; q++) acc[mt][n8][q] = 0.f;

    const int NC = 24;
    auto load_chunk = [&](int c, int stage) {
        int seg = c >> 3, kc = c & 7;
        const __nv_bfloat16* As = (seg == 2) ? Alo : Ahi;
        const __nv_bfloat16* Bs = (seg == 1) ? Blo : Bhi;
        uint32_t st = sbase + stage * 32768;
#pragma unroll
        for (int u8 = 0; u8 < 8; u8++) {
            int u = tid * 8 + u8;
            int isB = u >> 10;
            int uu = u & 1023;
            int r = uu >> 3, ch = uu & 7;
            const __nv_bfloat16* src = isB
                ? (Bs + (size_t)(cb * 128 + r) * DD + kc * 64 + ch * 8)
                : (As + (size_t)(mb * 128 + r) * DD + kc * 64 + ch * 8);
            uint32_t sa = st + isB * 16384 + r * 128 + ((ch ^ (r & 7)) << 4);
            cp_async16(sa, src);
        }
        cp_commit();
    };

    load_chunk(0, 0);
    for (int c = 0; c < NC; c++) {
        if (c + 1 < NC) load_chunk(c + 1, (c + 1) & 1);
        if (c + 1 < NC) cp_wait<1>(); else cp_wait<0>();
        __syncthreads();
        uint32_t sA = sbase + (c & 1) * 32768;
        uint32_t sB = sA + 16384;
#pragma unroll
        for (int k16 = 0; k16 < 4; k16++) {
            uint32_t a[2][4];
#pragma unroll
            for (int mt = 0; mt < 2; mt++) {
                uint32_t ad = sA + arow[mt] + (((k16 * 2 + akh) ^ axc[mt]) << 4);
                ldsm4(a[mt][0], a[mt][1], a[mt][2], a[mt][3], ad);
            }
#pragma unroll
            for (int j = 0; j < 4; j++) {
                uint32_t b0, b1, b2, b3;
                uint32_t bd = sB + brow[j] + (((k16 * 2 + bkh) ^ bxc[j]) << 4);
                ldsm4(b0, b1, b2, b3, bd);
                mma16816(acc[0][2 * j],     a[0][0], a[0][1], a[0][2], a[0][3], b0, b1);
                mma16816(acc[0][2 * j + 1], a[0][0], a[0][1], a[0][2], a[0][3], b2, b3);
                mma16816(acc[1][2 * j],     a[1][0], a[1][1], a[1][2], a[1][3], b0, b1);
                mma16816(acc[1][2 * j + 1], a[1][0], a[1][1], a[1][2], a[1][3], b2, b3);
            }
        }
        __syncthreads();
    }

    const int colw = cb * 128 + wn * 64;
    const int roww = mb * 128 + wm * 32;
#pragma unroll
    for (int mt = 0; mt < 2; mt++) {
#pragma unroll
        for (int n8 = 0; n8 < 8; n8++) {
            int col = colw + n8 * 8 + (lane & 3) * 2;
            int row = roww + mt * 16 + (lane >> 2);
            if (mode == 0) {
                int sect = col >> 9, d = col & 511;
                int h = d >> 6, hd = d & 63;
                float* dst = (sect == 0) ? g_q : ((sect == 1) ? g_k : g_v);
                int b = row >> 10, n = row & 1023;
                size_t base = ((size_t)((b * HH + h) * NN) + n) * HDIM + hd;
                *(float2*)&dst[base] = make_float2(acc[mt][n8][0], acc[mt][n8][1]);
                *(float2*)&dst[base + 8 * HDIM] = make_float2(acc[mt][n8][2], acc[mt][n8][3]);
            } else {
                float b0 = bias[col], b1 = bias[col + 1];
                *(float2*)&outp[(size_t)row * DD + col] =
                    make_float2(acc[mt][n8][0] + b0, acc[mt][n8][1] + b1);
                *(float2*)&outp[(size_t)(row + 8) * DD + col] =
                    make_float2(acc[mt][n8][2] + b0, acc[mt][n8][3] + b1);
            }
        }
    }
}

// ---------------- kernel 2: tensor-core edge-aware flash attention ----------------
// block = (b, h, 128 queries); 8 warps x 16 q rows; K-tile = 64 keys.
// S = QK^T via bf16x3 mma.sync; edge/gate/mask/softmax SIMT in accumulator layout;
// P repacked in-register as A fragments (flash identity); O += P@V via bf16x3 mma.
__global__ __launch_bounds__(256, 1) void attn_kernel(const float* __restrict__ edge,
                                                      const float* __restrict__ w_ep,
                                                      const float* __restrict__ w_eg,
                                                      const float* __restrict__ b_eg) {
    extern __shared__ __align__(128) char smraw[];
    __nv_bfloat16* sQh = (__nv_bfloat16*)smraw;        // QT x 64
    __nv_bfloat16* sQl = sQh + QT * 64;
    __nv_bfloat16* sKh = sQl + QT * 64;                // KT x 64 (key, d)
    __nv_bfloat16* sKl = sKh + KT * 64;
    __nv_bfloat16* sVh = sKl + KT * 64;                // KT x 64 transposed (d, key)
    __nv_bfloat16* sVl = sVh + KT * 64;
    int* skm = (int*)(sVl + KT * 64);

    const int b = blockIdx.z, h = blockIdx.y, qt = blockIdx.x;
    const int n0 = qt * QT;
    const int tid = threadIdx.x;
    const int lane = tid & 31;
    const int w = tid >> 5;
    const int wq0 = w * 16;

    float wep[EE], weg[EE];
#pragma unroll
    for (int e = 0; e < EE; e++) {
        wep[e] = __ldg(&w_ep[h * EE + e]);
        weg[e] = __ldg(&w_eg[h * EE + e]);
    }
    const float beg = __ldg(&b_eg[h]);
    const int anyv = g_any[b];

    // ---- stage Q (fp32 -> bf16 hi/lo, swizzled) ----
    const float* qsrc = g_q + ((size_t)(b * HH + h) * NN + n0) * HDIM;
    for (int u = tid; u < QT * 16; u += 256) {
        int r = u >> 4, c4 = (u & 15) * 4;
        float4 qv = *(const float4*)(qsrc + r * HDIM + c4);
        int idx = swz(r, c4);
        float vs[4] = {qv.x, qv.y, qv.z, qv.w};
#pragma unroll
        for (int j = 0; j < 4; j++) {
            __nv_bfloat16 hh = __float2bfloat16(vs[j]);
            sQh[idx + j] = hh;
            sQl[idx + j] = __float2bfloat16(vs[j] - __bfloat162float(hh));
        }
    }

    // row validity (per-warp rows: lane>>2 and +8)
    const int r_lo = lane >> 2;
    const int qv0 = g_mask[b * NN + n0 + wq0 + r_lo];
    const int qv1 = g_mask[b * NN + n0 + wq0 + r_lo + 8];
    const bool rowv0 = qv0 && anyv;
    const bool rowv1 = qv1 && anyv;

    float accO[8][4];
#pragma unroll
    for (int j = 0; j < 8; j++)
#pragma unroll
        for (int q = 0; q < 4; q++) accO[j][q] = 0.f;
    float mr0 = -1e30f, mr1 = -1e30f, sr0 = 0.f, sr1 = 0.f;

    const float* kbase = g_k + (size_t)(b * HH + h) * NN * HDIM;
    const float* vbase = g_v + (size_t)(b * HH + h) * NN * HDIM;

    const uint32_t uQh = smem_u32(sQh), uQl = smem_u32(sQl);
    const uint32_t uKh = smem_u32(sKh), uKl = smem_u32(sKl);
    const uint32_t uVh = smem_u32(sVh), uVl = smem_u32(sVl);

    for (int m0 = 0; m0 < NN; m0 += KT) {
        __syncthreads();
        // ---- stage K (row-major) and V (transposed), bf16 hi/lo ----
        for (int u = tid; u < KT * 16; u += 256) {
            int r = u >> 4, c4 = (u & 15) * 4;
            float4 kv = *(const float4*)(kbase + (size_t)(m0 + r) * HDIM + c4);
            int idx = swz(r, c4);
            float ks[4] = {kv.x, kv.y, kv.z, kv.w};
#pragma unroll
            for (int j = 0; j < 4; j++) {
                __nv_bfloat16 hh = __float2bfloat16(ks[j]);
                sKh[idx + j] = hh;
                sKl[idx + j] = __float2bfloat16(ks[j] - __bfloat162float(hh));
            }
            float4 vv = *(const float4*)(vbase + (size_t)(m0 + r) * HDIM + c4);
            float vsv[4] = {vv.x, vv.y, vv.z, vv.w};
#pragma unroll
            for (int j = 0; j < 4; j++) {      // element (d=c4+j, key=r)
                int ti = swz(c4 + j, r);
                __nv_bfloat16 hh = __float2bfloat16(vsv[j]);
                sVh[ti] = hh;
                sVl[ti] = __float2bfloat16(vsv[j] - __bfloat162float(hh));
            }
        }
        if (tid < KT) skm[tid] = g_mask[b * NN + m0 + tid];
        __syncthreads();

        // ---- S = Q K^T (bf16x3) ----
        float accS[8][4];
#pragma unroll
        for (int j = 0; j < 8; j++)
#pragma unroll
            for (int q = 0; q < 4; q++) accS[j][q] = 0.f;

#pragma unroll
        for (int s = 0; s < 4; s++) {
            int ra = wq0 + (lane & 15);
            int cha = (s * 2 + (lane >> 4)) ^ (ra & 7);
            uint32_t aoff = (uint32_t)(ra * 64 + (cha << 3)) * 2;
            uint32_t ah[4], al_[4];
            ldsm4(ah[0], ah[1], ah[2], ah[3], uQh + aoff);
            ldsm4(al_[0], al_[1], al_[2], al_[3], uQl + aoff);
            int rb = ((lane >> 4) << 3) + (lane & 7);
            int khb = s * 2 + ((lane >> 3) & 1);
#pragma unroll
            for (int g = 0; g < 4; g++) {
                int rn = g * 16 + rb;
                uint32_t boff = (uint32_t)(rn * 64 + ((khb ^ (rn & 7)) << 3)) * 2;
                uint32_t bh0, bh1, bh2, bh3, bl0, bl1, bl2, bl3;
                ldsm4(bh0, bh1, bh2, bh3, uKh + boff);
                ldsm4(bl0, bl1, bl2, bl3, uKl + boff);
                mma16816(accS[2 * g],     ah[0], ah[1], ah[2], ah[3], bh0, bh1);
                mma16816(accS[2 * g + 1], ah[0], ah[1], ah[2], ah[3], bh2, bh3);
                mma16816(accS[2 * g],     ah[0], ah[1], ah[2], ah[3], bl0, bl1);
                mma16816(accS[2 * g + 1], ah[0], ah[1], ah[2], ah[3], bl2, bl3);
                mma16816(accS[2 * g],     al_[0], al_[1], al_[2], al_[3], bh0, bh1);
                mma16816(accS[2 * g + 1], al_[0], al_[1], al_[2], al_[3], bh2, bh3);
            }
        }

        // ---- epilogue: scale + edge bias/gate + mask ----
        const int nr0 = n0 + wq0 + r_lo;
        const int nr1 = nr0 + 8;
#pragma unroll
        for (int j = 0; j < 8; j++) {
            int colL = j * 8 + (lane & 3) * 2;       // local key index (and +1)
            int kv0 = skm[colL], kv1 = skm[colL + 1];
            int cg = m0 + colL;
#pragma unroll
            for (int q = 0; q < 4; q++) {
                int nr = (q < 2) ? nr0 : nr1;
                bool rv = (q < 2) ? rowv0 : rowv1;
                int col = cg + (q & 1);
                bool kv = (q & 1) ? (kv1 != 0) : (kv0 != 0);
                const float* ep = edge + ((size_t)(b * NN + nr) * NN + col) * EE;
                float e0 = __ldg(ep), e1 = __ldg(ep + 1), e2 = __ldg(ep + 2),
                      e3 = __ldg(ep + 3), e4 = __ldg(ep + 4);
                float biasv = e0 * wep[0];
                biasv = fmaf(e1, wep[1], biasv);
                biasv = fmaf(e2, wep[2], biasv);
                biasv = fmaf(e3, wep[3], biasv);
                biasv = fmaf(e4, wep[4], biasv);
                float gv = fmaf(e0, weg[0], beg);
                gv = fmaf(e1, weg[1], gv);
                gv = fmaf(e2, weg[2], gv);
                gv = fmaf(e3, weg[3], gv);
                gv = fmaf(e4, weg[4], gv);
                float gate = __fdividef(1.f, 1.f + fast_exp(-gv));
                float s = fmaf(gate, biasv, accS[j][q] * 0.125f);
                bool pairv = rv && kv && ((q < 2) ? qv0 : qv1);
                accS[j][q] = rv ? (pairv ? s : -1e30f) : 0.0f;
            }
        }

        // ---- online softmax (rows r_lo and r_lo+8; quad = same row) ----
        float mx0 = -1e30f, mx1 = -1e30f;
#pragma unroll
        for (int j = 0; j < 8; j++) {
            mx0 = fmaxf(mx0, fmaxf(accS[j][0], accS[j][1]));
            mx1 = fmaxf(mx1, fmaxf(accS[j][2], accS[j][3]));
        }
        mx0 = fmaxf(mx0, __shfl_xor_sync(0xffffffffu, mx0, 1));
        mx0 = fmaxf(mx0, __shfl_xor_sync(0xffffffffu, mx0, 2));
        mx1 = fmaxf(mx1, __shfl_xor_sync(0xffffffffu, mx1, 1));
        mx1 = fmaxf(mx1, __shfl_xor_sync(0xffffffffu, mx1, 2));
        float mn0 = fmaxf(mr0, mx0), mn1 = fmaxf(mr1, mx1);
        float al0 = fast_exp(mr0 - mn0), al1 = fast_exp(mr1 - mn1);
        mr0 = mn0; mr1 = mn1;
        float ls0 = 0.f, ls1 = 0.f;
#pragma unroll
        for (int j = 0; j < 8; j++) {
            accS[j][0] = fast_exp(accS[j][0] - mn0);
            accS[j][1] = fast_exp(accS[j][1] - mn0);
            accS[j][2] = fast_exp(accS[j][2] - mn1);
            accS[j][3] = fast_exp(accS[j][3] - mn1);
            ls0 += accS[j][0] + accS[j][1];
            ls1 += accS[j][2] + accS[j][3];
        }
        ls0 += __shfl_xor_sync(0xffffffffu, ls0, 1);
        ls0 += __shfl_xor_sync(0xffffffffu, ls0, 2);
        ls1 += __shfl_xor_sync(0xffffffffu, ls1, 1);
        ls1 += __shfl_xor_sync(0xffffffffu, ls1, 2);
        sr0 = fmaf(sr0, al0, ls0);
        sr1 = fmaf(sr1, al1, ls1);
#pragma unroll
        for (int j = 0; j < 8; j++) {
            accO[j][0] *= al0; accO[j][1] *= al0;
            accO[j][2] *= al1; accO[j][3] *= al1;
        }

        // ---- O += P V (bf16x3, P from S-accumulator layout) ----
#pragma unroll
        for (int t = 0; t < 4; t++) {
            uint32_t ah[4], al_[4];
            pack_hilo(accS[2 * t][0],     accS[2 * t][1],     ah[0], al_[0]);
            pack_hilo(accS[2 * t][2],     accS[2 * t][3],     ah[1], al_[1]);
            pack_hilo(accS[2 * t + 1][0], accS[2 * t + 1][1], ah[2], al_[2]);
            pack_hilo(accS[2 * t + 1][2], accS[2 * t + 1][3], ah[3], al_[3]);
            int rb = ((lane >> 4) << 3) + (lane & 7);
            int khb = t * 2 + ((lane >> 3) & 1);
#pragma unroll
            for (int g = 0; g < 4; g++) {
                int rn = g * 16 + rb;                       // d row
                uint32_t boff = (uint32_t)(rn * 64 + ((khb ^ (rn & 7)) << 3)) * 2;
                uint32_t bh0, bh1, bh2, bh3, bl0, bl1, bl2, bl3;
                ldsm4(bh0, bh1, bh2, bh3, uVh + boff);
                ldsm4(bl0, bl1, bl2, bl3, uVl + boff);
                mma16816(accO[2 * g],     ah[0], ah[1], ah[2], ah[3], bh0, bh1);
                mma16816(accO[2 * g + 1], ah[0], ah[1], ah[2], ah[3], bh2, bh3);
                mma16816(accO[2 * g],     ah[0], ah[1], ah[2], ah[3], bl0, bl1);
                mma16816(accO[2 * g + 1], ah[0], ah[1], ah[2], ah[3], bl2, bl3);
                mma16816(accO[2 * g],     al_[0], al_[1], al_[2], al_[3], bh0, bh1);
                mma16816(accO[2 * g + 1], al_[0], al_[1], al_[2], al_[3], bh2, bh3);
            }
        }
    }

    // ---- final: normalize + emit bf16 hi/lo for proj GEMM ----
    float inv0 = __fdividef(1.f, sr0), inv1 = __fdividef(1.f, sr1);
    int nrow0 = n0 + wq0 + r_lo, nrow1 = nrow0 + 8;
#pragma unroll
    for (int j = 0; j < 8; j++) {
        int d0 = j * 8 + (lane & 3) * 2;
        size_t b0i = (size_t)(b * NN + nrow0) * DD + h * HDIM + d0;
        size_t b1i = (size_t)(b * NN + nrow1) * DD + h * HDIM + d0;
        float o00 = accO[j][0] * inv0, o01 = accO[j][1] * inv0;
        float o10 = accO[j][2] * inv1, o11 = accO[j][3] * inv1;
        uint32_t hi, lo;
        pack_hilo(o00, o01, hi, lo);
        *(uint32_t*)&g_atthi[b0i] = hi;
        *(uint32_t*)&g_attlo[b0i] = lo;
        pack_hilo(o10, o11, hi, lo);
        *(uint32_t*)&g_atthi[b1i] = hi;
        *(uint32_t*)&g_attlo[b1i] = lo;
    }
}

// ---------------- launch ----------------
extern "C" void kernel_launch(void* const* d_in, const int* in_sizes, int n_in,
                              void* d_out, int out_size) {
    const float* x      = (const float*)d_in[0];
    const float* edge   = (const float*)d_in[1];
    const void*  mask   = d_in[2];
    const float* w_qkv  = (const float*)d_in[3];
    const float* w_ep   = (const float*)d_in[4];
    const float* w_eg   = (const float*)d_in[5];
    const float* b_eg   = (const float*)d_in[6];
    const float* w_proj = (const float*)d_in[7];
    const float* b_proj = (const float*)d_in[8];
    float* out = (float*)d_out;

    static bool attr_done = false;
    if (!attr_done) {
        cudaFuncSetAttribute(mma_gemm_kernel, cudaFuncAttributeMaxDynamicSharedMemorySize, 65536);
        cudaFuncSetAttribute(attn_kernel, cudaFuncAttributeMaxDynamicSharedMemorySize, 66560);
        attr_done = true;
    }

    mask_prep_kernel<<<1, 1024>>>((const unsigned*)mask);

    cvt_kernel<<<(BB * NN * DD + 255) / 256, 256>>>(x, BB * NN * DD, 0);
    cvt_kernel<<<(3 * DD * DD + 255) / 256, 256>>>(w_qkv, 3 * DD * DD, 1);
    cvt_kernel<<<(DD * DD + 255) / 256, 256>>>(w_proj, DD * DD, 2);

    dim3 g1(12, 32);
    mma_gemm_kernel<<<g1, 256, 65536>>>(nullptr, nullptr, 0);

    dim3 ga(NN / QT, HH, BB);
    attn_kernel<<<ga, 256, 66560>>>(edge, w_ep, w_eg, b_eg);

    dim3 g2(4, 32);
    mma_gemm_kernel<<<g2, 256, 65536>>>(b_proj, out, 1);
}

// round 5
// speedup vs baseline: 2.4180x; 1.5197x over previous
#include <cuda_runtime.h>
#include <cuda_bf16.h>
#include <cstdint>

#define BB 4
#define NN 1024
#define DD 512
#define HH 8
#define EE 5
#define HDIM 64
#define QT 128
#define KT 64
#define NTILES (NN / KT)

// ---------------- scratch (device globals; no allocation allowed) ----------------
__device__ float g_v[BB * HH * NN * HDIM];
__device__ int   g_mask[BB * NN];
__device__ int   g_any[BB];
// pre-swizzled bf16 hi/lo operands for attention
__device__ __nv_bfloat16 g_qhi[BB * HH * NN * HDIM], g_qlo[BB * HH * NN * HDIM];
__device__ __nv_bfloat16 g_khi[BB * HH * NN * HDIM], g_klo[BB * HH * NN * HDIM];
__device__ __nv_bfloat16 g_vthi[BB * HH * NN * HDIM], g_vtlo[BB * HH * NN * HDIM];
// bf16 hi/lo splits for GEMMs
__device__ __nv_bfloat16 g_xhi[BB * NN * DD],   g_xlo[BB * NN * DD];
__device__ __nv_bfloat16 g_wqkvhi[3 * DD * DD], g_wqkvlo[3 * DD * DD];
__device__ __nv_bfloat16 g_atthi[BB * NN * DD], g_attlo[BB * NN * DD];
__device__ __nv_bfloat16 g_wprojhi[DD * DD],    g_wprojlo[DD * DD];

// ---------------- helpers ----------------
__device__ __forceinline__ uint32_t smem_u32(const void* p) {
    return (uint32_t)__cvta_generic_to_shared(p);
}
__device__ __forceinline__ void ldsm4(uint32_t& r0, uint32_t& r1, uint32_t& r2, uint32_t& r3,
                                      uint32_t a) {
    asm volatile("ldmatrix.sync.aligned.m8n8.x4.shared.b16 {%0,%1,%2,%3}, [%4];"
                 : "=r"(r0), "=r"(r1), "=r"(r2), "=r"(r3) : "r"(a));
}
__device__ __forceinline__ void mma16816(float* c, uint32_t a0, uint32_t a1, uint32_t a2,
                                         uint32_t a3, uint32_t b0, uint32_t b1) {
    asm volatile(
        "mma.sync.aligned.m16n8k16.row.col.f32.bf16.bf16.f32 "
        "{%0,%1,%2,%3}, {%4,%5,%6,%7}, {%8,%9}, {%0,%1,%2,%3};"
        : "+f"(c[0]), "+f"(c[1]), "+f"(c[2]), "+f"(c[3])
        : "r"(a0), "r"(a1), "r"(a2), "r"(a3), "r"(b0), "r"(b1));
}
__device__ __forceinline__ void cp_async16(uint32_t saddr, const void* gaddr) {
    asm volatile("cp.async.ca.shared.global [%0], [%1], 16;" :: "r"(saddr), "l"(gaddr));
}
__device__ __forceinline__ void cp_commit() {
    asm volatile("cp.async.commit_group;" ::: "memory");
}
template <int N>
__device__ __forceinline__ void cp_wait() {
    asm volatile("cp.async.wait_group %0;" :: "n"(N) : "memory");
}
__device__ __forceinline__ void pack_hilo(float p0, float p1, uint32_t& hi, uint32_t& lo) {
    __nv_bfloat16 h0 = __float2bfloat16(p0), h1 = __float2bfloat16(p1);
    hi = ((uint32_t)__bfloat16_as_ushort(h1) << 16) | (uint32_t)__bfloat16_as_ushort(h0);
    __nv_bfloat16 g0 = __float2bfloat16(p0 - __bfloat162float(h0));
    __nv_bfloat16 g1 = __float2bfloat16(p1 - __bfloat162float(h1));
    lo = ((uint32_t)__bfloat16_as_ushort(g1) << 16) | (uint32_t)__bfloat16_as_ushort(g0);
}

// ---------------- kernel 0: mask canonicalization ----------------
__global__ void mask_prep_kernel(const unsigned* __restrict__ mraw) {
    __shared__ int s_int, s_float;
    __shared__ int s_any[BB];
    int t = threadIdx.x;
    if (t == 0) { s_int = 1; s_float = 1; }
    if (t < BB) s_any[t] = 0;
    __syncthreads();
    unsigned v = mraw[t];
    if (v > 1u) atomicAnd(&s_int, 0);
    if (!(v == 0u || v == 0x3F800000u)) atomicAnd(&s_float, 0);
    __syncthreads();
    int mode = s_int ? 0 : (s_float ? 1 : 2);
    for (int i = t; i < BB * NN; i += 1024) {
        int val;
        if (mode == 0)      val = ((const int*)mraw)[i];
        else if (mode == 1) val = (((const unsigned*)mraw)[i] != 0u);
        else                val = ((const unsigned char*)mraw)[i];
        val = val ? 1 : 0;
        g_mask[i] = val;
        if (val) atomicOr(&s_any[i >> 10], 1);
    }
    __syncthreads();
    if (t < BB) g_any[t] = s_any[t];
}

// ---------------- kernel 0b: fp32 -> bf16 hi/lo split ----------------
__global__ void cvt_kernel(const float* __restrict__ src, int n, int which) {
    __nv_bfloat16* hi = (which == 0) ? g_xhi : (which == 1) ? g_wqkvhi : g_wprojhi;
    __nv_bfloat16* lo = (which == 0) ? g_xlo : (which == 1) ? g_wqkvlo : g_wprojlo;
    int i = blockIdx.x * 256 + threadIdx.x;
    if (i < n) {
        float v = src[i];
        __nv_bfloat16 h = __float2bfloat16(v);
        hi[i] = h;
        lo[i] = __float2bfloat16(v - __bfloat162float(h));
    }
}

// ---------------- mma.sync bf16x3 GEMM (round-3 core, new mode-0 epilogue) ----------------
__global__ __launch_bounds__(256) void mma_gemm_kernel(const float* __restrict__ bias,
                                                       float* __restrict__ outp, int mode) {
    extern __shared__ __align__(128) char sm[];
    const int tid = threadIdx.x;
    const int wid = tid >> 5, lane = tid & 31;
    const int wm = wid >> 1, wn = wid & 1;
    const int mb = blockIdx.y, cb = blockIdx.x;

    const __nv_bfloat16* Ahi = (mode == 0) ? g_xhi : g_atthi;
    const __nv_bfloat16* Alo = (mode == 0) ? g_xlo : g_attlo;
    const __nv_bfloat16* Bhi = (mode == 0) ? g_wqkvhi : g_wprojhi;
    const __nv_bfloat16* Blo = (mode == 0) ? g_wqkvlo : g_wprojlo;

    const uint32_t sbase = smem_u32(sm);

    int arow[2], axc[2];
#pragma unroll
    for (int mt = 0; mt < 2; mt++) {
        int r = wm * 32 + mt * 16 + (lane & 15);
        arow[mt] = r * 128;
        axc[mt] = r & 7;
    }
    const int akh = lane >> 4;
    int brow[4], bxc[4];
#pragma unroll
    for (int j = 0; j < 4; j++) {
        int r = wn * 64 + j * 16 + ((lane >> 4) << 3) + (lane & 7);
        brow[j] = r * 128;
        bxc[j] = r & 7;
    }
    const int bkh = (lane >> 3) & 1;

    float acc[2][8][4];
#pragma unroll
    for (int mt = 0; mt < 2; mt++)
#pragma unroll
        for (int n8 = 0; n8 < 8; n8++)
#pragma unroll
            for (int q = 0; q < 4; q++) acc[mt][n8][q] = 0.f;

    const int NC = 24;
    auto load_chunk = [&](int c, int stage) {
        int seg = c >> 3, kc = c & 7;
        const __nv_bfloat16* As = (seg == 2) ? Alo : Ahi;
        const __nv_bfloat16* Bs = (seg == 1) ? Blo : Bhi;
        uint32_t st = sbase + stage * 32768;
#pragma unroll
        for (int u8 = 0; u8 < 8; u8++) {
            int u = tid * 8 + u8;
            int isB = u >> 10;
            int uu = u & 1023;
            int r = uu >> 3, ch = uu & 7;
            const __nv_bfloat16* src = isB
                ? (Bs + (size_t)(cb * 128 + r) * DD + kc * 64 + ch * 8)
                : (As + (size_t)(mb * 128 + r) * DD + kc * 64 + ch * 8);
            uint32_t sa = st + isB * 16384 + r * 128 + ((ch ^ (r & 7)) << 4);
            cp_async16(sa, src);
        }
        cp_commit();
    };

    load_chunk(0, 0);
    for (int c = 0; c < NC; c++) {
        if (c + 1 < NC) load_chunk(c + 1, (c + 1) & 1);
        if (c + 1 < NC) cp_wait<1>(); else cp_wait<0>();
        __syncthreads();
        uint32_t sA = sbase + (c & 1) * 32768;
        uint32_t sB = sA + 16384;
#pragma unroll
        for (int k16 = 0; k16 < 4; k16++) {
            uint32_t a[2][4];
#pragma unroll
            for (int mt = 0; mt < 2; mt++) {
                uint32_t ad = sA + arow[mt] + (((k16 * 2 + akh) ^ axc[mt]) << 4);
                ldsm4(a[mt][0], a[mt][1], a[mt][2], a[mt][3], ad);
            }
#pragma unroll
            for (int j = 0; j < 4; j++) {
                uint32_t b0, b1, b2, b3;
                uint32_t bd = sB + brow[j] + (((k16 * 2 + bkh) ^ bxc[j]) << 4);
                ldsm4(b0, b1, b2, b3, bd);
                mma16816(acc[0][2 * j],     a[0][0], a[0][1], a[0][2], a[0][3], b0, b1);
                mma16816(acc[0][2 * j + 1], a[0][0], a[0][1], a[0][2], a[0][3], b2, b3);
                mma16816(acc[1][2 * j],     a[1][0], a[1][1], a[1][2], a[1][3], b0, b1);
                mma16816(acc[1][2 * j + 1], a[1][0], a[1][1], a[1][2], a[1][3], b2, b3);
            }
        }
        __syncthreads();
    }

    const int colw = cb * 128 + wn * 64;
    const int roww = mb * 128 + wm * 32;
#pragma unroll
    for (int mt = 0; mt < 2; mt++) {
#pragma unroll
        for (int n8 = 0; n8 < 8; n8++) {
            int col = colw + n8 * 8 + (lane & 3) * 2;
            int row = roww + mt * 16 + (lane >> 2);
            if (mode == 0) {
                int sect = col >> 9, d = col & 511;
                int h2 = d >> 6, hd = d & 63;
                int b2 = row >> 10, n = row & 1023;
                if (sect < 2) {
                    // emit Q/K directly as swizzle-permuted bf16 hi/lo
                    __nv_bfloat16* dh = (sect == 0) ? g_qhi : g_khi;
                    __nv_bfloat16* dl = (sect == 0) ? g_qlo : g_klo;
                    int ch = (hd >> 3) ^ (row & 7);
                    size_t e0 = ((size_t)(b2 * HH + h2) * NN + n) * HDIM + (ch << 3) + (hd & 7);
                    uint32_t hi, lo;
                    pack_hilo(acc[mt][n8][0], acc[mt][n8][1], hi, lo);
                    *(uint32_t*)&dh[e0] = hi;
                    *(uint32_t*)&dl[e0] = lo;
                    pack_hilo(acc[mt][n8][2], acc[mt][n8][3], hi, lo);
                    *(uint32_t*)&dh[e0 + 8 * HDIM] = hi;
                    *(uint32_t*)&dl[e0 + 8 * HDIM] = lo;
                } else {
                    size_t base = ((size_t)(b2 * HH + h2) * NN + n) * HDIM + hd;
                    *(float2*)&g_v[base] = make_float2(acc[mt][n8][0], acc[mt][n8][1]);
                    *(float2*)&g_v[base + 8 * HDIM] = make_float2(acc[mt][n8][2], acc[mt][n8][3]);
                }
            } else {
                float b0 = bias[col], b1 = bias[col + 1];
                *(float2*)&outp[(size_t)row * DD + col] =
                    make_float2(acc[mt][n8][0] + b0, acc[mt][n8][1] + b1);
                *(float2*)&outp[(size_t)(row + 8) * DD + col] =
                    make_float2(acc[mt][n8][2] + b0, acc[mt][n8][3] + b1);
            }
        }
    }
}

// ---------------- kernel 1b: V transpose -> pre-swizzled bf16 hi/lo tiles ----------------
// block = (tile t, bh). Vt layout: tile-major, row d (0..63), 64 keys, chunk-permuted.
__global__ __launch_bounds__(256) void vprep_kernel() {
    __shared__ float Vf[64][68];
    const int t = blockIdx.x, bh = blockIdx.y;
    const int tid = threadIdx.x;
    const int m0 = t * KT;
    const float* src = g_v + ((size_t)bh * NN + m0) * HDIM;
    for (int u = tid; u < 1024; u += 256) {
        int key = u >> 4, c4 = (u & 15) * 4;
        *(float4*)&Vf[key][c4] = *(const float4*)(src + key * HDIM + c4);
    }
    __syncthreads();
    __nv_bfloat16* dh = g_vthi + (((size_t)bh * NTILES + t) * 64) * 64;
    __nv_bfloat16* dl = g_vtlo + (((size_t)bh * NTILES + t) * 64) * 64;
    for (int u = tid; u < 1024; u += 256) {
        int d = u >> 4, k4 = (u & 15) * 4;      // keys k4..k4+3 in row d
        uint32_t h0, l0, h1, l1;
        pack_hilo(Vf[k4 + 0][d], Vf[k4 + 1][d], h0, l0);
        pack_hilo(Vf[k4 + 2][d], Vf[k4 + 3][d], h1, l1);
        int chp = (k4 >> 3) ^ (d & 7);
        size_t off = (size_t)d * 64 + (chp << 3) + (k4 & 7);
        *(uint2*)&dh[off] = make_uint2(h0, h1);
        *(uint2*)&dl[off] = make_uint2(l0, l1);
    }
}

// ---------------- kernel 2: tensor-core edge-aware flash attention ----------------
// Double-buffered cp.async of pre-swizzled bf16 tiles; MUFU sigmoid/exp; float2 edge loads.
__global__ __launch_bounds__(256) void attn_kernel(const float* __restrict__ edge,
                                                   const float* __restrict__ w_ep,
                                                   const float* __restrict__ w_eg,
                                                   const float* __restrict__ b_eg) {
    extern __shared__ __align__(128) char smraw[];
    // layout: Qh 16K | Ql 16K | stage0 {Kh,Kl,Vh,Vl} 32K | stage1 32K | masks 512B
    const uint32_t sb = smem_u32(smraw);
    const uint32_t uQh = sb, uQl = sb + 16384;
    int* skm = (int*)(smraw + 98304);

    const int b = blockIdx.z, h = blockIdx.y, qt = blockIdx.x;
    const int bh = b * HH + h;
    const int n0 = qt * QT;
    const int tid = threadIdx.x;
    const int lane = tid & 31;
    const int w = tid >> 5;
    const int wq0 = w * 16;

    float wep[EE], weg[EE];
#pragma unroll
    for (int e = 0; e < EE; e++) {
        wep[e] = __ldg(&w_ep[h * EE + e]);
        weg[e] = __ldg(&w_eg[h * EE + e]);
    }
    const float beg = __ldg(&b_eg[h]);
    const int anyv = g_any[b];

    const __nv_bfloat16* qh = g_qhi + ((size_t)bh * NN + n0) * HDIM;
    const __nv_bfloat16* ql = g_qlo + ((size_t)bh * NN + n0) * HDIM;
    const __nv_bfloat16* kh = g_khi + (size_t)bh * NN * HDIM;
    const __nv_bfloat16* kl = g_klo + (size_t)bh * NN * HDIM;
    const __nv_bfloat16* vh = g_vthi + (size_t)bh * NN * HDIM;
    const __nv_bfloat16* vl = g_vtlo + (size_t)bh * NN * HDIM;

    auto issue_tile = [&](int t, int st) {
        uint32_t base = sb + 32768 + st * 32768;
        size_t ko = (size_t)t * KT * HDIM;   // 4096 elements per tile
#pragma unroll
        for (int i = 0; i < 2; i++) {
            int u = tid * 2 + i;             // 0..511 16B units
            cp_async16(base + u * 16, kh + ko + u * 8);
            cp_async16(base + 8192 + u * 16, kl + ko + u * 8);
            cp_async16(base + 16384 + u * 16, vh + ko + u * 8);
            cp_async16(base + 24576 + u * 16, vl + ko + u * 8);
        }
        if (tid < 16) cp_async16(smem_u32(skm + st * 64) + tid * 16,
                                 g_mask + b * NN + t * KT + tid * 4);
    };

    // prologue: Q copy + tile0 (group 0), tile1 (group 1)
#pragma unroll
    for (int i = 0; i < 4; i++) {
        int u = tid * 4 + i;                 // 0..1023 units of 16B
        cp_async16(uQh + u * 16, qh + u * 8);
        cp_async16(uQl + u * 16, ql + u * 8);
    }
    issue_tile(0, 0);
    cp_commit();
    issue_tile(1, 1);
    cp_commit();

    const int r_lo = lane >> 2;
    const int qv0 = g_mask[b * NN + n0 + wq0 + r_lo];
    const int qv1 = g_mask[b * NN + n0 + wq0 + r_lo + 8];
    const bool rowv0 = qv0 && anyv;
    const bool rowv1 = qv1 && anyv;

    float accO[8][4];
#pragma unroll
    for (int j = 0; j < 8; j++)
#pragma unroll
        for (int q = 0; q < 4; q++) accO[j][q] = 0.f;
    float mr0 = -1e30f, mr1 = -1e30f, sr0 = 0.f, sr1 = 0.f;

    const int nr0 = n0 + wq0 + r_lo;
    const int nr1 = nr0 + 8;
    const float* erow0 = edge + (size_t)(b * NN + nr0) * NN * EE;
    const float* erow1 = edge + (size_t)(b * NN + nr1) * NN * EE;

    auto edge_score = [&](float e0, float e1, float e2, float e3, float e4,
                          float sv, bool rv, int kvf) -> float {
        float biasv = e0 * wep[0];
        biasv = fmaf(e1, wep[1], biasv);
        biasv = fmaf(e2, wep[2], biasv);
        biasv = fmaf(e3, wep[3], biasv);
        biasv = fmaf(e4, wep[4], biasv);
        float gv = fmaf(e0, weg[0], beg);
        gv = fmaf(e1, weg[1], gv);
        gv = fmaf(e2, weg[2], gv);
        gv = fmaf(e3, weg[3], gv);
        gv = fmaf(e4, weg[4], gv);
        float gate = __fdividef(1.f, 1.f + __expf(-gv));
        float s = fmaf(gate, biasv, sv * 0.125f);
        return rv ? (kvf ? s : -1e30f) : 0.0f;
    };

    for (int t = 0; t < NTILES; t++) {
        cp_wait<1>();
        __syncthreads();
        const int st = t & 1;
        const int m0 = t * KT;
        const uint32_t uKh = sb + 32768 + st * 32768;
        const uint32_t uKl = uKh + 8192;
        const uint32_t uVh = uKh + 16384;
        const uint32_t uVl = uKh + 24576;
        const int* skm_st = skm + st * 64;

        // ---- S = Q K^T (bf16x3) ----
        float accS[8][4];
#pragma unroll
        for (int j = 0; j < 8; j++)
#pragma unroll
            for (int q = 0; q < 4; q++) accS[j][q] = 0.f;

#pragma unroll
        for (int s = 0; s < 4; s++) {
            int ra = wq0 + (lane & 15);
            int cha = (s * 2 + (lane >> 4)) ^ (ra & 7);
            uint32_t aoff = (uint32_t)(ra * 64 + (cha << 3)) * 2;
            uint32_t ah[4], al_[4];
            ldsm4(ah[0], ah[1], ah[2], ah[3], uQh + aoff);
            ldsm4(al_[0], al_[1], al_[2], al_[3], uQl + aoff);
            int rb = ((lane >> 4) << 3) + (lane & 7);
            int khb = s * 2 + ((lane >> 3) & 1);
#pragma unroll
            for (int g = 0; g < 4; g++) {
                int rn = g * 16 + rb;
                uint32_t boff = (uint32_t)(rn * 64 + ((khb ^ (rn & 7)) << 3)) * 2;
                uint32_t bh0, bh1, bh2, bh3, bl0, bl1, bl2, bl3;
                ldsm4(bh0, bh1, bh2, bh3, uKh + boff);
                ldsm4(bl0, bl1, bl2, bl3, uKl + boff);
                mma16816(accS[2 * g],     ah[0], ah[1], ah[2], ah[3], bh0, bh1);
                mma16816(accS[2 * g + 1], ah[0], ah[1], ah[2], ah[3], bh2, bh3);
                mma16816(accS[2 * g],     ah[0], ah[1], ah[2], ah[3], bl0, bl1);
                mma16816(accS[2 * g + 1], ah[0], ah[1], ah[2], ah[3], bl2, bl3);
                mma16816(accS[2 * g],     al_[0], al_[1], al_[2], al_[3], bh0, bh1);
                mma16816(accS[2 * g + 1], al_[0], al_[1], al_[2], al_[3], bh2, bh3);
            }
        }

        // ---- epilogue: scale + edge bias/gate + mask (float2 loads, MUFU sigmoid) ----
#pragma unroll
        for (int j = 0; j < 8; j++) {
            int colL = j * 8 + (lane & 3) * 2;
            int cg = m0 + colL;
            int kv0 = skm_st[colL], kv1 = skm_st[colL + 1];
            const float2* p0 = (const float2*)(erow0 + (size_t)cg * EE);
            float2 a0 = __ldg(p0), a1 = __ldg(p0 + 1), a2 = __ldg(p0 + 2),
                   a3 = __ldg(p0 + 3), a4 = __ldg(p0 + 4);
            accS[j][0] = edge_score(a0.x, a0.y, a1.x, a1.y, a2.x, accS[j][0], rowv0, kv0);
            accS[j][1] = edge_score(a2.y, a3.x, a3.y, a4.x, a4.y, accS[j][1], rowv0, kv1);
            const float2* p1 = (const float2*)(erow1 + (size_t)cg * EE);
            a0 = __ldg(p1); a1 = __ldg(p1 + 1); a2 = __ldg(p1 + 2);
            a3 = __ldg(p1 + 3); a4 = __ldg(p1 + 4);
            accS[j][2] = edge_score(a0.x, a0.y, a1.x, a1.y, a2.x, accS[j][2], rowv1, kv0);
            accS[j][3] = edge_score(a2.y, a3.x, a3.y, a4.x, a4.y, accS[j][3], rowv1, kv1);
        }

        // ---- online softmax (MUFU exp) ----
        float mx0 = -1e30f, mx1 = -1e30f;
#pragma unroll
        for (int j = 0; j < 8; j++) {
            mx0 = fmaxf(mx0, fmaxf(accS[j][0], accS[j][1]));
            mx1 = fmaxf(mx1, fmaxf(accS[j][2], accS[j][3]));
        }
        mx0 = fmaxf(mx0, __shfl_xor_sync(0xffffffffu, mx0, 1));
        mx0 = fmaxf(mx0, __shfl_xor_sync(0xffffffffu, mx0, 2));
        mx1 = fmaxf(mx1, __shfl_xor_sync(0xffffffffu, mx1, 1));
        mx1 = fmaxf(mx1, __shfl_xor_sync(0xffffffffu, mx1, 2));
        float mn0 = fmaxf(mr0, mx0), mn1 = fmaxf(mr1, mx1);
        float al0 = __expf(mr0 - mn0), al1 = __expf(mr1 - mn1);
        mr0 = mn0; mr1 = mn1;
        float ls0 = 0.f, ls1 = 0.f;
#pragma unroll
        for (int j = 0; j < 8; j++) {
            accS[j][0] = __expf(accS[j][0] - mn0);
            accS[j][1] = __expf(accS[j][1] - mn0);
            accS[j][2] = __expf(accS[j][2] - mn1);
            accS[j][3] = __expf(accS[j][3] - mn1);
            ls0 += accS[j][0] + accS[j][1];
            ls1 += accS[j][2] + accS[j][3];
        }
        ls0 += __shfl_xor_sync(0xffffffffu, ls0, 1);
        ls0 += __shfl_xor_sync(0xffffffffu, ls0, 2);
        ls1 += __shfl_xor_sync(0xffffffffu, ls1, 1);
        ls1 += __shfl_xor_sync(0xffffffffu, ls1, 2);
        sr0 = fmaf(sr0, al0, ls0);
        sr1 = fmaf(sr1, al1, ls1);
#pragma unroll
        for (int j = 0; j < 8; j++) {
            accO[j][0] *= al0; accO[j][1] *= al0;
            accO[j][2] *= al1; accO[j][3] *= al1;
        }

        // ---- O += P V (bf16x3, P from S-accumulator layout) ----
#pragma unroll
        for (int tt = 0; tt < 4; tt++) {
            uint32_t ah[4], al_[4];
            pack_hilo(accS[2 * tt][0],     accS[2 * tt][1],     ah[0], al_[0]);
            pack_hilo(accS[2 * tt][2],     accS[2 * tt][3],     ah[1], al_[1]);
            pack_hilo(accS[2 * tt + 1][0], accS[2 * tt + 1][1], ah[2], al_[2]);
            pack_hilo(accS[2 * tt + 1][2], accS[2 * tt + 1][3], ah[3], al_[3]);
            int rb = ((lane >> 4) << 3) + (lane & 7);
            int khb = tt * 2 + ((lane >> 3) & 1);
#pragma unroll
            for (int g = 0; g < 4; g++) {
                int rn = g * 16 + rb;
                uint32_t boff = (uint32_t)(rn * 64 + ((khb ^ (rn & 7)) << 3)) * 2;
                uint32_t bh0, bh1, bh2, bh3, bl0, bl1, bl2, bl3;
                ldsm4(bh0, bh1, bh2, bh3, uVh + boff);
                ldsm4(bl0, bl1, bl2, bl3, uVl + boff);
                mma16816(accO[2 * g],     ah[0], ah[1], ah[2], ah[3], bh0, bh1);
                mma16816(accO[2 * g + 1], ah[0], ah[1], ah[2], ah[3], bh2, bh3);
                mma16816(accO[2 * g],     ah[0], ah[1], ah[2], ah[3], bl0, bl1);
                mma16816(accO[2 * g + 1], ah[0], ah[1], ah[2], ah[3], bl2, bl3);
                mma16816(accO[2 * g],     al_[0], al_[1], al_[2], al_[3], bh0, bh1);
                mma16816(accO[2 * g + 1], al_[0], al_[1], al_[2], al_[3], bh2, bh3);
            }
        }

        __syncthreads();
        if (t + 2 < NTILES) issue_tile(t + 2, st);
        cp_commit();
    }

    // ---- final: normalize + emit bf16 hi/lo for proj GEMM ----
    float inv0 = __fdividef(1.f, sr0), inv1 = __fdividef(1.f, sr1);
#pragma unroll
    for (int j = 0; j < 8; j++) {
        int d0 = j * 8 + (lane & 3) * 2;
        size_t b0i = (size_t)(b * NN + nr0) * DD + h * HDIM + d0;
        size_t b1i = (size_t)(b * NN + nr1) * DD + h * HDIM + d0;
        uint32_t hi, lo;
        pack_hilo(accO[j][0] * inv0, accO[j][1] * inv0, hi, lo);
        *(uint32_t*)&g_atthi[b0i] = hi;
        *(uint32_t*)&g_attlo[b0i] = lo;
        pack_hilo(accO[j][2] * inv1, accO[j][3] * inv1, hi, lo);
        *(uint32_t*)&g_atthi[b1i] = hi;
        *(uint32_t*)&g_attlo[b1i] = lo;
    }
}

// ---------------- launch ----------------
extern "C" void kernel_launch(void* const* d_in, const int* in_sizes, int n_in,
                              void* d_out, int out_size) {
    const float* x      = (const float*)d_in[0];
    const float* edge   = (const float*)d_in[1];
    const void*  mask   = d_in[2];
    const float* w_qkv  = (const float*)d_in[3];
    const float* w_ep   = (const float*)d_in[4];
    const float* w_eg   = (const float*)d_in[5];
    const float* b_eg   = (const float*)d_in[6];
    const float* w_proj = (const float*)d_in[7];
    const float* b_proj = (const float*)d_in[8];
    float* out = (float*)d_out;

    static bool attr_done = false;
    if (!attr_done) {
        cudaFuncSetAttribute(mma_gemm_kernel, cudaFuncAttributeMaxDynamicSharedMemorySize, 65536);
        cudaFuncSetAttribute(attn_kernel, cudaFuncAttributeMaxDynamicSharedMemorySize, 98816);
        attr_done = true;
    }

    mask_prep_kernel<<<1, 1024>>>((const unsigned*)mask);

    cvt_kernel<<<(BB * NN * DD + 255) / 256, 256>>>(x, BB * NN * DD, 0);
    cvt_kernel<<<(3 * DD * DD + 255) / 256, 256>>>(w_qkv, 3 * DD * DD, 1);
    cvt_kernel<<<(DD * DD + 255) / 256, 256>>>(w_proj, DD * DD, 2);

    dim3 g1(12, 32);
    mma_gemm_kernel<<<g1, 256, 65536>>>(nullptr, nullptr, 0);

    dim3 gv(NTILES, BB * HH);
    vprep_kernel<<<gv, 256>>>();

    dim3 ga(NN / QT, HH, BB);
    attn_kernel<<<ga, 256, 98816>>>(edge, w_ep, w_eg, b_eg);

    dim3 g2(4, 32);
    mma_gemm_kernel<<<g2, 256, 65536>>>(b_proj, out, 1);
}

// round 6
// speedup vs baseline: 2.4936x; 1.0313x over previous
#include <cuda_runtime.h>
#include <cuda_bf16.h>
#include <cstdint>

#define BB 4
#define NN 1024
#define DD 512
#define HH 8
#define EE 5
#define HDIM 64
#define QT 128
#define KT 64
#define NTILES (NN / KT)

// ---------------- scratch (device globals; no allocation allowed) ----------------
__device__ float g_v[BB * HH * NN * HDIM];
__device__ int   g_mask[BB * NN];
__device__ int   g_any[BB];
__device__ float g_G[(size_t)BB * HH * NN * NN];   // precomputed gate*bias per (b,h,n,m)
// pre-swizzled bf16 hi/lo operands for attention
__device__ __nv_bfloat16 g_qhi[BB * HH * NN * HDIM], g_qlo[BB * HH * NN * HDIM];
__device__ __nv_bfloat16 g_khi[BB * HH * NN * HDIM], g_klo[BB * HH * NN * HDIM];
__device__ __nv_bfloat16 g_vthi[BB * HH * NN * HDIM], g_vtlo[BB * HH * NN * HDIM];
// bf16 hi/lo splits for GEMMs
__device__ __nv_bfloat16 g_xhi[BB * NN * DD],   g_xlo[BB * NN * DD];
__device__ __nv_bfloat16 g_wqkvhi[3 * DD * DD], g_wqkvlo[3 * DD * DD];
__device__ __nv_bfloat16 g_atthi[BB * NN * DD], g_attlo[BB * NN * DD];
__device__ __nv_bfloat16 g_wprojhi[DD * DD],    g_wprojlo[DD * DD];

// ---------------- helpers ----------------
__device__ __forceinline__ uint32_t smem_u32(const void* p) {
    return (uint32_t)__cvta_generic_to_shared(p);
}
__device__ __forceinline__ void ldsm4(uint32_t& r0, uint32_t& r1, uint32_t& r2, uint32_t& r3,
                                      uint32_t a) {
    asm volatile("ldmatrix.sync.aligned.m8n8.x4.shared.b16 {%0,%1,%2,%3}, [%4];"
                 : "=r"(r0), "=r"(r1), "=r"(r2), "=r"(r3) : "r"(a));
}
__device__ __forceinline__ void mma16816(float* c, uint32_t a0, uint32_t a1, uint32_t a2,
                                         uint32_t a3, uint32_t b0, uint32_t b1) {
    asm volatile(
        "mma.sync.aligned.m16n8k16.row.col.f32.bf16.bf16.f32 "
        "{%0,%1,%2,%3}, {%4,%5,%6,%7}, {%8,%9}, {%0,%1,%2,%3};"
        : "+f"(c[0]), "+f"(c[1]), "+f"(c[2]), "+f"(c[3])
        : "r"(a0), "r"(a1), "r"(a2), "r"(a3), "r"(b0), "r"(b1));
}
__device__ __forceinline__ void cp_async16(uint32_t saddr, const void* gaddr) {
    asm volatile("cp.async.ca.shared.global [%0], [%1], 16;" :: "r"(saddr), "l"(gaddr));
}
__device__ __forceinline__ void cp_commit() {
    asm volatile("cp.async.commit_group;" ::: "memory");
}
template <int N>
__device__ __forceinline__ void cp_wait() {
    asm volatile("cp.async.wait_group %0;" :: "n"(N) : "memory");
}
__device__ __forceinline__ void pack_hilo(float p0, float p1, uint32_t& hi, uint32_t& lo) {
    __nv_bfloat16 h0 = __float2bfloat16(p0), h1 = __float2bfloat16(p1);
    hi = ((uint32_t)__bfloat16_as_ushort(h1) << 16) | (uint32_t)__bfloat16_as_ushort(h0);
    __nv_bfloat16 g0 = __float2bfloat16(p0 - __bfloat162float(h0));
    __nv_bfloat16 g1 = __float2bfloat16(p1 - __bfloat162float(h1));
    lo = ((uint32_t)__bfloat16_as_ushort(g1) << 16) | (uint32_t)__bfloat16_as_ushort(g0);
}

// ---------------- kernel 0: mask canonicalization ----------------
__global__ void mask_prep_kernel(const unsigned* __restrict__ mraw) {
    __shared__ int s_int, s_float;
    __shared__ int s_any[BB];
    int t = threadIdx.x;
    if (t == 0) { s_int = 1; s_float = 1; }
    if (t < BB) s_any[t] = 0;
    __syncthreads();
    unsigned v = mraw[t];
    if (v > 1u) atomicAnd(&s_int, 0);
    if (!(v == 0u || v == 0x3F800000u)) atomicAnd(&s_float, 0);
    __syncthreads();
    int mode = s_int ? 0 : (s_float ? 1 : 2);
    for (int i = t; i < BB * NN; i += 1024) {
        int val;
        if (mode == 0)      val = ((const int*)mraw)[i];
        else if (mode == 1) val = (((const unsigned*)mraw)[i] != 0u);
        else                val = ((const unsigned char*)mraw)[i];
        val = val ? 1 : 0;
        g_mask[i] = val;
        if (val) atomicOr(&s_any[i >> 10], 1);
    }
    __syncthreads();
    if (t < BB) g_any[t] = s_any[t];
}

// ---------------- kernel 0b: fp32 -> bf16 hi/lo split ----------------
__global__ void cvt_kernel(const float* __restrict__ src, int n, int which) {
    __nv_bfloat16* hi = (which == 0) ? g_xhi : (which == 1) ? g_wqkvhi : g_wprojhi;
    __nv_bfloat16* lo = (which == 0) ? g_xlo : (which == 1) ? g_wqkvlo : g_wprojlo;
    int i = blockIdx.x * 256 + threadIdx.x;
    if (i < n) {
        float v = src[i];
        __nv_bfloat16 h = __float2bfloat16(v);
        hi[i] = h;
        lo[i] = __float2bfloat16(v - __bfloat162float(h));
    }
}

// ---------------- kernel 0c: edge -> G[b,h,n,m] = sigmoid(edge.weg+beg)*(edge.wep) ----------------
// block = (m-tile 128, n, b), 128 threads. Edge read ONCE; all 8 heads computed;
// smem transpose for coalesced per-head stores.
__global__ __launch_bounds__(128) void edge_prep_kernel(const float* __restrict__ edge,
                                                        const float* __restrict__ w_ep,
                                                        const float* __restrict__ w_eg,
                                                        const float* __restrict__ b_eg) {
    __shared__ float sG[HH][129];
    const int m0 = blockIdx.x * 128, n = blockIdx.y, b = blockIdx.z;
    const int t = threadIdx.x;
    const float* ep = edge + ((size_t)(b * NN + n) * NN + m0 + t) * EE;
    float e0 = __ldg(ep), e1 = __ldg(ep + 1), e2 = __ldg(ep + 2),
          e3 = __ldg(ep + 3), e4 = __ldg(ep + 4);
#pragma unroll
    for (int h = 0; h < HH; h++) {
        float biasv = e0 * __ldg(&w_ep[h * EE + 0]);
        biasv = fmaf(e1, __ldg(&w_ep[h * EE + 1]), biasv);
        biasv = fmaf(e2, __ldg(&w_ep[h * EE + 2]), biasv);
        biasv = fmaf(e3, __ldg(&w_ep[h * EE + 3]), biasv);
        biasv = fmaf(e4, __ldg(&w_ep[h * EE + 4]), biasv);
        float gv = fmaf(e0, __ldg(&w_eg[h * EE + 0]), __ldg(&b_eg[h]));
        gv = fmaf(e1, __ldg(&w_eg[h * EE + 1]), gv);
        gv = fmaf(e2, __ldg(&w_eg[h * EE + 2]), gv);
        gv = fmaf(e3, __ldg(&w_eg[h * EE + 3]), gv);
        gv = fmaf(e4, __ldg(&w_eg[h * EE + 4]), gv);
        float gate = __fdividef(1.f, 1.f + __expf(-gv));
        sG[h][t] = gate * biasv;
    }
    __syncthreads();
#pragma unroll
    for (int h = 0; h < HH; h++) {
        g_G[((size_t)(b * HH + h) * NN + n) * NN + m0 + t] = sG[h][t];
    }
}

// ---------------- mma.sync bf16x3 GEMM ----------------
__global__ __launch_bounds__(256) void mma_gemm_kernel(const float* __restrict__ bias,
                                                       float* __restrict__ outp, int mode) {
    extern __shared__ __align__(128) char sm[];
    const int tid = threadIdx.x;
    const int wid = tid >> 5, lane = tid & 31;
    const int wm = wid >> 1, wn = wid & 1;
    const int mb = blockIdx.y, cb = blockIdx.x;

    const __nv_bfloat16* Ahi = (mode == 0) ? g_xhi : g_atthi;
    const __nv_bfloat16* Alo = (mode == 0) ? g_xlo : g_attlo;
    const __nv_bfloat16* Bhi = (mode == 0) ? g_wqkvhi : g_wprojhi;
    const __nv_bfloat16* Blo = (mode == 0) ? g_wqkvlo : g_wprojlo;

    const uint32_t sbase = smem_u32(sm);

    int arow[2], axc[2];
#pragma unroll
    for (int mt = 0; mt < 2; mt++) {
        int r = wm * 32 + mt * 16 + (lane & 15);
        arow[mt] = r * 128;
        axc[mt] = r & 7;
    }
    const int akh = lane >> 4;
    int brow[4], bxc[4];
#pragma unroll
    for (int j = 0; j < 4; j++) {
        int r = wn * 64 + j * 16 + ((lane >> 4) << 3) + (lane & 7);
        brow[j] = r * 128;
        bxc[j] = r & 7;
    }
    const int bkh = (lane >> 3) & 1;

    float acc[2][8][4];
#pragma unroll
    for (int mt = 0; mt < 2; mt++)
#pragma unroll
        for (int n8 = 0; n8 < 8; n8++)
#pragma unroll
            for (int q = 0; q < 4; q++) acc[mt][n8][q] = 0.f;

    const int NC = 24;
    auto load_chunk = [&](int c, int stage) {
        int seg = c >> 3, kc = c & 7;
        const __nv_bfloat16* As = (seg == 2) ? Alo : Ahi;
        const __nv_bfloat16* Bs = (seg == 1) ? Blo : Bhi;
        uint32_t st = sbase + stage * 32768;
#pragma unroll
        for (int u8 = 0; u8 < 8; u8++) {
            int u = tid * 8 + u8;
            int isB = u >> 10;
            int uu = u & 1023;
            int r = uu >> 3, ch = uu & 7;
            const __nv_bfloat16* src = isB
                ? (Bs + (size_t)(cb * 128 + r) * DD + kc * 64 + ch * 8)
                : (As + (size_t)(mb * 128 + r) * DD + kc * 64 + ch * 8);
            uint32_t sa = st + isB * 16384 + r * 128 + ((ch ^ (r & 7)) << 4);
            cp_async16(sa, src);
        }
        cp_commit();
    };

    load_chunk(0, 0);
    for (int c = 0; c < NC; c++) {
        if (c + 1 < NC) load_chunk(c + 1, (c + 1) & 1);
        if (c + 1 < NC) cp_wait<1>(); else cp_wait<0>();
        __syncthreads();
        uint32_t sA = sbase + (c & 1) * 32768;
        uint32_t sB = sA + 16384;
#pragma unroll
        for (int k16 = 0; k16 < 4; k16++) {
            uint32_t a[2][4];
#pragma unroll
            for (int mt = 0; mt < 2; mt++) {
                uint32_t ad = sA + arow[mt] + (((k16 * 2 + akh) ^ axc[mt]) << 4);
                ldsm4(a[mt][0], a[mt][1], a[mt][2], a[mt][3], ad);
            }
#pragma unroll
            for (int j = 0; j < 4; j++) {
                uint32_t b0, b1, b2, b3;
                uint32_t bd = sB + brow[j] + (((k16 * 2 + bkh) ^ bxc[j]) << 4);
                ldsm4(b0, b1, b2, b3, bd);
                mma16816(acc[0][2 * j],     a[0][0], a[0][1], a[0][2], a[0][3], b0, b1);
                mma16816(acc[0][2 * j + 1], a[0][0], a[0][1], a[0][2], a[0][3], b2, b3);
                mma16816(acc[1][2 * j],     a[1][0], a[1][1], a[1][2], a[1][3], b0, b1);
                mma16816(acc[1][2 * j + 1], a[1][0], a[1][1], a[1][2], a[1][3], b2, b3);
            }
        }
        __syncthreads();
    }

    const int colw = cb * 128 + wn * 64;
    const int roww = mb * 128 + wm * 32;
#pragma unroll
    for (int mt = 0; mt < 2; mt++) {
#pragma unroll
        for (int n8 = 0; n8 < 8; n8++) {
            int col = colw + n8 * 8 + (lane & 3) * 2;
            int row = roww + mt * 16 + (lane >> 2);
            if (mode == 0) {
                int sect = col >> 9, d = col & 511;
                int h2 = d >> 6, hd = d & 63;
                int b2 = row >> 10, n = row & 1023;
                if (sect < 2) {
                    __nv_bfloat16* dh = (sect == 0) ? g_qhi : g_khi;
                    __nv_bfloat16* dl = (sect == 0) ? g_qlo : g_klo;
                    int ch = (hd >> 3) ^ (row & 7);
                    size_t e0 = ((size_t)(b2 * HH + h2) * NN + n) * HDIM + (ch << 3) + (hd & 7);
                    uint32_t hi, lo;
                    pack_hilo(acc[mt][n8][0], acc[mt][n8][1], hi, lo);
                    *(uint32_t*)&dh[e0] = hi;
                    *(uint32_t*)&dl[e0] = lo;
                    pack_hilo(acc[mt][n8][2], acc[mt][n8][3], hi, lo);
                    *(uint32_t*)&dh[e0 + 8 * HDIM] = hi;
                    *(uint32_t*)&dl[e0 + 8 * HDIM] = lo;
                } else {
                    size_t base = ((size_t)(b2 * HH + h2) * NN + n) * HDIM + hd;
                    *(float2*)&g_v[base] = make_float2(acc[mt][n8][0], acc[mt][n8][1]);
                    *(float2*)&g_v[base + 8 * HDIM] = make_float2(acc[mt][n8][2], acc[mt][n8][3]);
                }
            } else {
                float b0 = bias[col], b1 = bias[col + 1];
                *(float2*)&outp[(size_t)row * DD + col] =
                    make_float2(acc[mt][n8][0] + b0, acc[mt][n8][1] + b1);
                *(float2*)&outp[(size_t)(row + 8) * DD + col] =
                    make_float2(acc[mt][n8][2] + b0, acc[mt][n8][3] + b1);
            }
        }
    }
}

// ---------------- kernel 1b: V transpose -> pre-swizzled bf16 hi/lo tiles ----------------
__global__ __launch_bounds__(256) void vprep_kernel() {
    __shared__ float Vf[64][68];
    const int t = blockIdx.x, bh = blockIdx.y;
    const int tid = threadIdx.x;
    const int m0 = t * KT;
    const float* src = g_v + ((size_t)bh * NN + m0) * HDIM;
    for (int u = tid; u < 1024; u += 256) {
        int key = u >> 4, c4 = (u & 15) * 4;
        *(float4*)&Vf[key][c4] = *(const float4*)(src + key * HDIM + c4);
    }
    __syncthreads();
    __nv_bfloat16* dh = g_vthi + (((size_t)bh * NTILES + t) * 64) * 64;
    __nv_bfloat16* dl = g_vtlo + (((size_t)bh * NTILES + t) * 64) * 64;
    for (int u = tid; u < 1024; u += 256) {
        int d = u >> 4, k4 = (u & 15) * 4;
        uint32_t h0, l0, h1, l1;
        pack_hilo(Vf[k4 + 0][d], Vf[k4 + 1][d], h0, l0);
        pack_hilo(Vf[k4 + 2][d], Vf[k4 + 3][d], h1, l1);
        int chp = (k4 >> 3) ^ (d & 7);
        size_t off = (size_t)d * 64 + (chp << 3) + (k4 & 7);
        *(uint2*)&dh[off] = make_uint2(h0, h1);
        *(uint2*)&dl[off] = make_uint2(l0, l1);
    }
}

// ---------------- kernel 2: tensor-core edge-aware flash attention ----------------
__global__ __launch_bounds__(256) void attn_kernel() {
    extern __shared__ __align__(128) char smraw[];
    const uint32_t sb = smem_u32(smraw);
    const uint32_t uQh = sb, uQl = sb + 16384;
    int* skm = (int*)(smraw + 98304);

    const int b = blockIdx.z, h = blockIdx.y, qt = blockIdx.x;
    const int bh = b * HH + h;
    const int n0 = qt * QT;
    const int tid = threadIdx.x;
    const int lane = tid & 31;
    const int w = tid >> 5;
    const int wq0 = w * 16;

    const int anyv = g_any[b];

    const __nv_bfloat16* qh = g_qhi + ((size_t)bh * NN + n0) * HDIM;
    const __nv_bfloat16* ql = g_qlo + ((size_t)bh * NN + n0) * HDIM;
    const __nv_bfloat16* kh = g_khi + (size_t)bh * NN * HDIM;
    const __nv_bfloat16* kl = g_klo + (size_t)bh * NN * HDIM;
    const __nv_bfloat16* vh = g_vthi + (size_t)bh * NN * HDIM;
    const __nv_bfloat16* vl = g_vtlo + (size_t)bh * NN * HDIM;

    auto issue_tile = [&](int t, int st) {
        uint32_t base = sb + 32768 + st * 32768;
        size_t ko = (size_t)t * KT * HDIM;
#pragma unroll
        for (int i = 0; i < 2; i++) {
            int u = tid * 2 + i;
            cp_async16(base + u * 16, kh + ko + u * 8);
            cp_async16(base + 8192 + u * 16, kl + ko + u * 8);
            cp_async16(base + 16384 + u * 16, vh + ko + u * 8);
            cp_async16(base + 24576 + u * 16, vl + ko + u * 8);
        }
        if (tid < 16) cp_async16(smem_u32(skm + st * 64) + tid * 16,
                                 g_mask + b * NN + t * KT + tid * 4);
    };

#pragma unroll
    for (int i = 0; i < 4; i++) {
        int u = tid * 4 + i;
        cp_async16(uQh + u * 16, qh + u * 8);
        cp_async16(uQl + u * 16, ql + u * 8);
    }
    issue_tile(0, 0);
    cp_commit();
    issue_tile(1, 1);
    cp_commit();

    const int r_lo = lane >> 2;
    const int qv0 = g_mask[b * NN + n0 + wq0 + r_lo];
    const int qv1 = g_mask[b * NN + n0 + wq0 + r_lo + 8];
    const bool rowv0 = qv0 && anyv;
    const bool rowv1 = qv1 && anyv;

    float accO[8][4];
#pragma unroll
    for (int j = 0; j < 8; j++)
#pragma unroll
        for (int q = 0; q < 4; q++) accO[j][q] = 0.f;
    float mr0 = -1e30f, mr1 = -1e30f, sr0 = 0.f, sr1 = 0.f;

    const int nr0 = n0 + wq0 + r_lo;
    const int nr1 = nr0 + 8;
    const float* Grow0 = g_G + ((size_t)bh * NN + nr0) * NN;
    const float* Grow1 = g_G + ((size_t)bh * NN + nr1) * NN;

    for (int t = 0; t < NTILES; t++) {
        cp_wait<1>();
        __syncthreads();
        const int st = t & 1;
        const int m0 = t * KT;
        const uint32_t uKh = sb + 32768 + st * 32768;
        const uint32_t uKl = uKh + 8192;
        const uint32_t uVh = uKh + 16384;
        const uint32_t uVl = uKh + 24576;
        const int* skm_st = skm + st * 64;

        // ---- S = Q K^T (bf16x3) ----
        float accS[8][4];
#pragma unroll
        for (int j = 0; j < 8; j++)
#pragma unroll
            for (int q = 0; q < 4; q++) accS[j][q] = 0.f;

#pragma unroll
        for (int s = 0; s < 4; s++) {
            int ra = wq0 + (lane & 15);
            int cha = (s * 2 + (lane >> 4)) ^ (ra & 7);
            uint32_t aoff = (uint32_t)(ra * 64 + (cha << 3)) * 2;
            uint32_t ah[4], al_[4];
            ldsm4(ah[0], ah[1], ah[2], ah[3], uQh + aoff);
            ldsm4(al_[0], al_[1], al_[2], al_[3], uQl + aoff);
            int rb = ((lane >> 4) << 3) + (lane & 7);
            int khb = s * 2 + ((lane >> 3) & 1);
#pragma unroll
            for (int g = 0; g < 4; g++) {
                int rn = g * 16 + rb;
                uint32_t boff = (uint32_t)(rn * 64 + ((khb ^ (rn & 7)) << 3)) * 2;
                uint32_t bh0, bh1, bh2, bh3, bl0, bl1, bl2, bl3;
                ldsm4(bh0, bh1, bh2, bh3, uKh + boff);
                ldsm4(bl0, bl1, bl2, bl3, uKl + boff);
                mma16816(accS[2 * g],     ah[0], ah[1], ah[2], ah[3], bh0, bh1);
                mma16816(accS[2 * g + 1], ah[0], ah[1], ah[2], ah[3], bh2, bh3);
                mma16816(accS[2 * g],     ah[0], ah[1], ah[2], ah[3], bl0, bl1);
                mma16816(accS[2 * g + 1], ah[0], ah[1], ah[2], ah[3], bl2, bl3);
                mma16816(accS[2 * g],     al_[0], al_[1], al_[2], al_[3], bh0, bh1);
                mma16816(accS[2 * g + 1], al_[0], al_[1], al_[2], al_[3], bh2, bh3);
            }
        }

        // ---- epilogue: scale + precomputed G + mask ----
#pragma unroll
        for (int j = 0; j < 8; j++) {
            int colL = j * 8 + (lane & 3) * 2;
            int cg = m0 + colL;
            int kv0 = skm_st[colL], kv1 = skm_st[colL + 1];
            float2 gv0 = __ldg((const float2*)(Grow0 + cg));
            float2 gv1 = __ldg((const float2*)(Grow1 + cg));
            float s00 = fmaf(accS[j][0], 0.125f, gv0.x);
            float s01 = fmaf(accS[j][1], 0.125f, gv0.y);
            float s10 = fmaf(accS[j][2], 0.125f, gv1.x);
            float s11 = fmaf(accS[j][3], 0.125f, gv1.y);
            accS[j][0] = rowv0 ? (kv0 ? s00 : -1e30f) : 0.0f;
            accS[j][1] = rowv0 ? (kv1 ? s01 : -1e30f) : 0.0f;
            accS[j][2] = rowv1 ? (kv0 ? s10 : -1e30f) : 0.0f;
            accS[j][3] = rowv1 ? (kv1 ? s11 : -1e30f) : 0.0f;
        }

        // ---- online softmax (MUFU exp) ----
        float mx0 = -1e30f, mx1 = -1e30f;
#pragma unroll
        for (int j = 0; j < 8; j++) {
            mx0 = fmaxf(mx0, fmaxf(accS[j][0], accS[j][1]));
            mx1 = fmaxf(mx1, fmaxf(accS[j][2], accS[j][3]));
        }
        mx0 = fmaxf(mx0, __shfl_xor_sync(0xffffffffu, mx0, 1));
        mx0 = fmaxf(mx0, __shfl_xor_sync(0xffffffffu, mx0, 2));
        mx1 = fmaxf(mx1, __shfl_xor_sync(0xffffffffu, mx1, 1));
        mx1 = fmaxf(mx1, __shfl_xor_sync(0xffffffffu, mx1, 2));
        float mn0 = fmaxf(mr0, mx0), mn1 = fmaxf(mr1, mx1);
        float al0 = __expf(mr0 - mn0), al1 = __expf(mr1 - mn1);
        mr0 = mn0; mr1 = mn1;
        float ls0 = 0.f, ls1 = 0.f;
#pragma unroll
        for (int j = 0; j < 8; j++) {
            accS[j][0] = __expf(accS[j][0] - mn0);
            accS[j][1] = __expf(accS[j][1] - mn0);
            accS[j][2] = __expf(accS[j][2] - mn1);
            accS[j][3] = __expf(accS[j][3] - mn1);
            ls0 += accS[j][0] + accS[j][1];
            ls1 += accS[j][2] + accS[j][3];
        }
        ls0 += __shfl_xor_sync(0xffffffffu, ls0, 1);
        ls0 += __shfl_xor_sync(0xffffffffu, ls0, 2);
        ls1 += __shfl_xor_sync(0xffffffffu, ls1, 1);
        ls1 += __shfl_xor_sync(0xffffffffu, ls1, 2);
        sr0 = fmaf(sr0, al0, ls0);
        sr1 = fmaf(sr1, al1, ls1);
#pragma unroll
        for (int j = 0; j < 8; j++) {
            accO[j][0] *= al0; accO[j][1] *= al0;
            accO[j][2] *= al1; accO[j][3] *= al1;
        }

        // ---- O += P V (bf16x3) ----
#pragma unroll
        for (int tt = 0; tt < 4; tt++) {
            uint32_t ah[4], al_[4];
            pack_hilo(accS[2 * tt][0],     accS[2 * tt][1],     ah[0], al_[0]);
            pack_hilo(accS[2 * tt][2],     accS[2 * tt][3],     ah[1], al_[1]);
            pack_hilo(accS[2 * tt + 1][0], accS[2 * tt + 1][1], ah[2], al_[2]);
            pack_hilo(accS[2 * tt + 1][2], accS[2 * tt + 1][3], ah[3], al_[3]);
            int rb = ((lane >> 4) << 3) + (lane & 7);
            int khb = tt * 2 + ((lane >> 3) & 1);
#pragma unroll
            for (int g = 0; g < 4; g++) {
                int rn = g * 16 + rb;
                uint32_t boff = (uint32_t)(rn * 64 + ((khb ^ (rn & 7)) << 3)) * 2;
                uint32_t bh0, bh1, bh2, bh3, bl0, bl1, bl2, bl3;
                ldsm4(bh0, bh1, bh2, bh3, uVh + boff);
                ldsm4(bl0, bl1, bl2, bl3, uVl + boff);
                mma16816(accO[2 * g],     ah[0], ah[1], ah[2], ah[3], bh0, bh1);
                mma16816(accO[2 * g + 1], ah[0], ah[1], ah[2], ah[3], bh2, bh3);
                mma16816(accO[2 * g],     ah[0], ah[1], ah[2], ah[3], bl0, bl1);
                mma16816(accO[2 * g + 1], ah[0], ah[1], ah[2], ah[3], bl2, bl3);
                mma16816(accO[2 * g],     al_[0], al_[1], al_[2], al_[3], bh0, bh1);
                mma16816(accO[2 * g + 1], al_[0], al_[1], al_[2], al_[3], bh2, bh3);
            }
        }

        __syncthreads();
        if (t + 2 < NTILES) issue_tile(t + 2, st);
        cp_commit();
    }

    // ---- final: normalize + emit bf16 hi/lo for proj GEMM ----
    float inv0 = __fdividef(1.f, sr0), inv1 = __fdividef(1.f, sr1);
#pragma unroll
    for (int j = 0; j < 8; j++) {
        int d0 = j * 8 + (lane & 3) * 2;
        size_t b0i = (size_t)(b * NN + nr0) * DD + h * HDIM + d0;
        size_t b1i = (size_t)(b * NN + nr1) * DD + h * HDIM + d0;
        uint32_t hi, lo;
        pack_hilo(accO[j][0] * inv0, accO[j][1] * inv0, hi, lo);
        *(uint32_t*)&g_atthi[b0i] = hi;
        *(uint32_t*)&g_attlo[b0i] = lo;
        pack_hilo(accO[j][2] * inv1, accO[j][3] * inv1, hi, lo);
        *(uint32_t*)&g_atthi[b1i] = hi;
        *(uint32_t*)&g_attlo[b1i] = lo;
    }
}

// ---------------- launch ----------------
extern "C" void kernel_launch(void* const* d_in, const int* in_sizes, int n_in,
                              void* d_out, int out_size) {
    const float* x      = (const float*)d_in[0];
    const float* edge   = (const float*)d_in[1];
    const void*  mask   = d_in[2];
    const float* w_qkv  = (const float*)d_in[3];
    const float* w_ep   = (const float*)d_in[4];
    const float* w_eg   = (const float*)d_in[5];
    const float* b_eg   = (const float*)d_in[6];
    const float* w_proj = (const float*)d_in[7];
    const float* b_proj = (const float*)d_in[8];
    float* out = (float*)d_out;

    static bool attr_done = false;
    if (!attr_done) {
        cudaFuncSetAttribute(mma_gemm_kernel, cudaFuncAttributeMaxDynamicSharedMemorySize, 65536);
        cudaFuncSetAttribute(attn_kernel, cudaFuncAttributeMaxDynamicSharedMemorySize, 98816);
        attr_done = true;
    }

    mask_prep_kernel<<<1, 1024>>>((const unsigned*)mask);

    cvt_kernel<<<(BB * NN * DD + 255) / 256, 256>>>(x, BB * NN * DD, 0);
    cvt_kernel<<<(3 * DD * DD + 255) / 256, 256>>>(w_qkv, 3 * DD * DD, 1);
    cvt_kernel<<<(DD * DD + 255) / 256, 256>>>(w_proj, DD * DD, 2);

    dim3 ge(NN / 128, NN, BB);
    edge_prep_kernel<<<ge, 128>>>(edge, w_ep, w_eg, b_eg);

    dim3 g1(12, 32);
    mma_gemm_kernel<<<g1, 256, 65536>>>(nullptr, nullptr, 0);

    dim3 gv(NTILES, BB * HH);
    vprep_kernel<<<gv, 256>>>();

    dim3 ga(NN / QT, HH, BB);
    attn_kernel<<<ga, 256, 98816>>>();

    dim3 g2(4, 32);
    mma_gemm_kernel<<<g2, 256, 65536>>>(b_proj, out, 1);
}